// round 8
// baseline (speedup 1.0000x reference)
#include <cuda_runtime.h>
#include <cstdint>
#include <cstddef>

// Problem constants
#define BB 4
#define SS 2048
#define DD 1024
#define HH 16
#define LL 8
#define VV 8192
#define HDIM 64
#define MTOK (BB*SS)   // 8192 tokens

typedef unsigned long long ull;

// ---------------------------------------------------------------------------
// Static device scratch (no allocations allowed)
// ---------------------------------------------------------------------------
__device__ float    g_x  [(size_t)MTOK * DD];           // residual fp32
__device__ float    g_qkv[(size_t)MTOK * 3 * DD];       // qkv fp32
__device__ __align__(16) uint32_t g_ah[(size_t)MTOK * DD / 2];       // act hi bf16
__device__ __align__(16) uint32_t g_al[(size_t)MTOK * DD / 2];       // act lo bf16
__device__ __align__(16) uint32_t g_fh[(size_t)MTOK * 4 * DD / 2];   // fc hi
__device__ __align__(16) uint32_t g_fl[(size_t)MTOK * 4 * DD / 2];   // fc lo
__device__ __align__(16) uint32_t g_bh[(size_t)VV * DD / 2];         // weight hi
__device__ __align__(16) uint32_t g_bl[(size_t)VV * DD / 2];         // weight lo

// ---------------------------------------------------------------------------
// Packed f32x2 helpers
// ---------------------------------------------------------------------------
__device__ __forceinline__ void fma2(ull& d, ull a, ull b) {
    asm("fma.rn.f32x2 %0, %1, %2, %0;" : "+l"(d) : "l"(a), "l"(b));
}
__device__ __forceinline__ ull mul2(ull a, ull b) {
    ull d; asm("mul.rn.f32x2 %0, %1, %2;" : "=l"(d) : "l"(a), "l"(b)); return d;
}
__device__ __forceinline__ ull pack2(float x, float y) {
    ull d; asm("mov.b64 %0, {%1, %2};" : "=l"(d) : "f"(x), "f"(y)); return d;
}
__device__ __forceinline__ float2 unpack2(ull v) {
    float2 r; asm("mov.b64 {%0, %1}, %2;" : "=f"(r.x), "=f"(r.y) : "l"(v)); return r;
}

__device__ __forceinline__ float gelu_f(float x) {
    float z = 0.7978845608028654f * (x + 0.044715f * x * x * x);
    float e = __expf(2.0f * z);
    float th = 1.0f - 2.0f / (e + 1.0f);
    return 0.5f * x * (1.0f + th);
}

// bf16x2 pack: {hi(y) | lo(x)}
__device__ __forceinline__ uint32_t bf2(float lo, float hi) {
    uint32_t r; asm("cvt.rn.bf16x2.f32 %0, %1, %2;" : "=r"(r) : "f"(hi), "f"(lo)); return r;
}

__device__ __forceinline__ uint32_t smem_u32(const void* p) {
    uint32_t a;
    asm("{ .reg .u64 t; cvta.to.shared.u64 t, %1; cvt.u32.u64 %0, t; }" : "=r"(a) : "l"(p));
    return a;
}

// ---------------------------------------------------------------------------
// mma.sync / ldmatrix / cp.async (sm_80-compatible path)
// ---------------------------------------------------------------------------
__device__ __forceinline__ void ldsm4(uint32_t* r, uint32_t addr) {
    asm volatile("ldmatrix.sync.aligned.m8n8.x4.shared.b16 {%0,%1,%2,%3}, [%4];"
        : "=r"(r[0]), "=r"(r[1]), "=r"(r[2]), "=r"(r[3]) : "r"(addr));
}
__device__ __forceinline__ void mma16816(float* c, const uint32_t* a, const uint32_t* b) {
    asm volatile(
        "mma.sync.aligned.m16n8k16.row.col.f32.bf16.bf16.f32 "
        "{%0,%1,%2,%3}, {%4,%5,%6,%7}, {%8,%9}, {%0,%1,%2,%3};"
        : "+f"(c[0]), "+f"(c[1]), "+f"(c[2]), "+f"(c[3])
        : "r"(a[0]), "r"(a[1]), "r"(a[2]), "r"(a[3]), "r"(b[0]), "r"(b[1]));
}
__device__ __forceinline__ void cpa16(uint32_t dst, const void* src) {
    size_t g = __cvta_generic_to_global(src);
    asm volatile("cp.async.cg.shared.global [%0], [%1], 16;" :: "r"(dst), "l"(g) : "memory");
}
#define CPA_COMMIT() asm volatile("cp.async.commit_group;" ::: "memory")
#define CPA_WAIT1()  asm volatile("cp.async.wait_group 1;"  ::: "memory")

// fp32x4 -> bf16 hi (8B) + bf16 lo residual (8B)
__device__ __forceinline__ void cvt_store(void* hi, void* lo, float4 v) {
    uint32_t h0 = bf2(v.x, v.y);
    uint32_t h1 = bf2(v.z, v.w);
    float bx = __uint_as_float(h0 << 16);
    float by = __uint_as_float(h0 & 0xffff0000u);
    float bz = __uint_as_float(h1 << 16);
    float bw = __uint_as_float(h1 & 0xffff0000u);
    uint32_t l0 = bf2(v.x - bx, v.y - by);
    uint32_t l1 = bf2(v.z - bz, v.w - bw);
    *(ull*)hi = ((ull)h1 << 32) | h0;
    *(ull*)lo = ((ull)l1 << 32) | l0;
}

// ---------------------------------------------------------------------------
// Weight conversion: fp32 -> bf16 hi/lo, 4 elems/thread
// ---------------------------------------------------------------------------
__global__ void cvt_w(const float* __restrict__ W, uint32_t* __restrict__ hi,
                      uint32_t* __restrict__ lo, int n4) {
    int i = blockIdx.x * 256 + threadIdx.x;
    if (i >= n4) return;
    float4 v = ((const float4*)W)[i];
    cvt_store((ull*)hi + i, (ull*)lo + i, v);
}

// ---------------------------------------------------------------------------
// Embedding
// ---------------------------------------------------------------------------
__global__ void embed_k(const int* __restrict__ idx, const float* __restrict__ wte,
                        const float* __restrict__ wpe, float* __restrict__ x) {
    int row = blockIdx.x;
    int s   = row & (SS - 1);
    int t   = threadIdx.x;
    int tok = idx[row];
    float4 a = ((const float4*)(wte + (size_t)tok * DD))[t];
    float4 p = ((const float4*)(wpe + (size_t)s * DD))[t];
    ((float4*)(x + (size_t)row * DD))[t] =
        make_float4(a.x + p.x, a.y + p.y, a.z + p.z, a.w + p.w);
}

// ---------------------------------------------------------------------------
// LayerNorm -> split bf16 output (GEMM A operand)
// ---------------------------------------------------------------------------
__global__ void ln_k(const float* __restrict__ x, const float* __restrict__ w,
                     const float* __restrict__ b, uint32_t* __restrict__ ohi,
                     uint32_t* __restrict__ olo) {
    int row = blockIdx.x;
    int t   = threadIdx.x;
    float4 v = ((const float4*)(x + (size_t)row * DD))[t];
    float s = v.x + v.y + v.z + v.w;
    float q = v.x * v.x + v.y * v.y + v.z * v.z + v.w * v.w;
    #pragma unroll
    for (int off = 16; off; off >>= 1) {
        s += __shfl_xor_sync(0xffffffffu, s, off);
        q += __shfl_xor_sync(0xffffffffu, q, off);
    }
    __shared__ float ss[8], sq[8];
    __shared__ float smu, srs;
    int wid = t >> 5;
    if ((t & 31) == 0) { ss[wid] = s; sq[wid] = q; }
    __syncthreads();
    if (t == 0) {
        float S = 0.f, Q = 0.f;
        #pragma unroll
        for (int i = 0; i < 8; i++) { S += ss[i]; Q += sq[i]; }
        float mu  = S * (1.0f / DD);
        float var = Q * (1.0f / DD) - mu * mu;
        smu = mu;
        srs = rsqrtf(var + 1e-5f);
    }
    __syncthreads();
    float mu = smu, r = srs;
    float4 wv = ((const float4*)w)[t];
    float4 bv = ((const float4*)b)[t];
    float4 out;
    out.x = (v.x - mu) * r * wv.x + bv.x;
    out.y = (v.y - mu) * r * wv.y + bv.y;
    out.z = (v.z - mu) * r * wv.z + bv.z;
    out.w = (v.w - mu) * r * wv.w + bv.w;
    size_t i = (size_t)row * (DD / 4) + t;
    cvt_store((ull*)ohi + i, (ull*)olo + i, out);
}

// ---------------------------------------------------------------------------
// Tensor-core NT GEMM on pre-split bf16: C = (Ah+Al)(Bh+Bl)^T (3 terms).
// CTA 128x128, K-step 32, 3-stage cp.async pipeline (32KB/stage), 2 CTAs/SM.
// 64B smem rows; swizzle slot = chunk ^ ((row>>1)&3) — conflict-free for both
// ldmatrix 8-row phases and cp.async stores.
// EPI: 0 = fp32 +bias, 1 = gelu(+bias) -> bf16 hi/lo, 2 = fp32 += acc+bias,
//      3 = fp32 plain
// ---------------------------------------------------------------------------
#define STAGE 32768
#define PL_AH 0
#define PL_AL 8192
#define PL_BH 16384
#define PL_BL 24576
#define GEMM_SMEM (3*STAGE)

template<int EPI>
__global__ void __launch_bounds__(256, 2)
gemm_bf(const char* __restrict__ Ah, const char* __restrict__ Al,
        const char* __restrict__ Bh, const char* __restrict__ Bl,
        const float* __restrict__ bias, float* __restrict__ C,
        uint32_t* __restrict__ Chi, uint32_t* __restrict__ Clo,
        int M, int N, int K)
{
    extern __shared__ __align__(16) char sm[];
    int tid  = threadIdx.x;
    int lane = tid & 31;
    int w    = tid >> 5;
    int wm   = w & 1;           // 64-row group
    int wn   = w >> 1;          // 32-col group
    int bn = blockIdx.x << 7, bm = blockIdx.y << 7;
    uint32_t smb = smem_u32(sm);

    float acc[4][4][4];
    #pragma unroll
    for (int i = 0; i < 4; i++)
        #pragma unroll
        for (int j = 0; j < 4; j++)
            #pragma unroll
            for (int r = 0; r < 4; r++) acc[i][j][r] = 0.f;

    int nk = K >> 5;
    int lr = tid >> 1;            // 0..127 tile row
    int q0 = (tid & 1) << 1;      // chunk base 0 or 2
    size_t arow = (size_t)(bm + lr) * K;
    size_t brow = (size_t)(bn + lr) * K;
    int sw = (lr >> 1) & 3;

    auto fill = [&](int slot, int ks) {
        int kc = ks << 5;
        uint32_t sb = smb + slot * STAGE + lr * 64;
        #pragma unroll
        for (int c = 0; c < 2; c++) {
            int q = q0 + c;
            uint32_t d = sb + ((q ^ sw) << 4);
            size_t ao = (arow + kc + q * 8) * 2;
            size_t bo = (brow + kc + q * 8) * 2;
            cpa16(d + PL_AH, Ah + ao);
            cpa16(d + PL_AL, Al + ao);
            cpa16(d + PL_BH, Bh + bo);
            cpa16(d + PL_BL, Bl + bo);
        }
    };
    fill(0, 0); CPA_COMMIT();
    fill(1, 1); CPA_COMMIT();

    for (int t = 0; t < nk; t++) {
        CPA_WAIT1();
        __syncthreads();
        if (t + 2 < nk) fill((t + 2) % 3, t + 2);
        CPA_COMMIT();

        uint32_t base = smb + (t % 3) * STAGE;
        #pragma unroll
        for (int kh = 0; kh < 2; kh++) {
            int cch = kh * 2 + (lane >> 4);
            uint32_t ahf[4][4], alf[4][4];
            #pragma unroll
            for (int mi = 0; mi < 4; mi++) {
                int row = wm * 64 + mi * 16 + (lane & 15);
                uint32_t ad = base + row * 64 + ((cch ^ ((row >> 1) & 3)) << 4);
                ldsm4(ahf[mi], ad + PL_AH);
                ldsm4(alf[mi], ad + PL_AL);
            }
            uint32_t bhq[2][4], blq[2][4];
            #pragma unroll
            for (int np = 0; np < 2; np++) {
                int row = wn * 32 + np * 16 + (lane & 15);
                uint32_t bd = base + row * 64 + ((cch ^ ((row >> 1) & 3)) << 4);
                ldsm4(bhq[np], bd + PL_BH);
                ldsm4(blq[np], bd + PL_BL);
            }
            uint32_t bhf[4][2], blf[4][2];
            #pragma unroll
            for (int np = 0; np < 2; np++)
                #pragma unroll
                for (int sdx = 0; sdx < 2; sdx++) {
                    bhf[np * 2 + sdx][0] = bhq[np][sdx];
                    bhf[np * 2 + sdx][1] = bhq[np][sdx + 2];
                    blf[np * 2 + sdx][0] = blq[np][sdx];
                    blf[np * 2 + sdx][1] = blq[np][sdx + 2];
                }
            #pragma unroll
            for (int mi = 0; mi < 4; mi++)
                #pragma unroll
                for (int ni = 0; ni < 4; ni++) {
                    mma16816(acc[mi][ni], ahf[mi], bhf[ni]);
                    mma16816(acc[mi][ni], ahf[mi], blf[ni]);
                    mma16816(acc[mi][ni], alf[mi], bhf[ni]);
                }
        }
    }

    // Epilogue: thread owns rows (r0, r0+8) x cols (c, c+1) per (mi,ni) tile
    int rbase = bm + wm * 64 + (lane >> 2);
    int cbase = bn + wn * 32 + ((lane & 3) << 1);
    #pragma unroll
    for (int mi = 0; mi < 4; mi++) {
        #pragma unroll
        for (int ni = 0; ni < 4; ni++) {
            float* cc = acc[mi][ni];
            int col  = cbase + ni * 8;
            int row0 = rbase + mi * 16;
            float b0 = 0.f, b1 = 0.f;
            if (EPI != 3) { b0 = bias[col]; b1 = bias[col + 1]; }
            #pragma unroll
            for (int half = 0; half < 2; half++) {
                int row = row0 + half * 8;
                float vx = cc[half * 2] + b0;
                float vy = cc[half * 2 + 1] + b1;
                if (EPI == 1) {
                    vx = gelu_f(vx); vy = gelu_f(vy);
                    uint32_t hv = bf2(vx, vy);
                    float rx = vx - __uint_as_float(hv << 16);
                    float ry = vy - __uint_as_float(hv & 0xffff0000u);
                    uint32_t lv = bf2(rx, ry);
                    size_t idx = ((size_t)row * N + col) >> 1;
                    Chi[idx] = hv;
                    Clo[idx] = lv;
                } else {
                    float* cp = C + (size_t)row * N + col;
                    if (EPI == 2) {
                        float2 o = *(const float2*)cp;
                        vx += o.x; vy += o.y;
                    }
                    *(float2*)cp = make_float2(vx, vy);
                }
            }
        }
    }
}

// ---------------------------------------------------------------------------
// Flash attention (causal). 128 q-rows/block, 256 threads: lane pair
// (2r, 2r+1) owns row r, 32 head-dims each. Dot closed by shfl_xor(1).
// Output written as split bf16 (proj GEMM A operand).
// ---------------------------------------------------------------------------
#define ATTN_SMEM ((64*64*2 + 128*65) * 4)

__global__ __launch_bounds__(256) void attn_k(const float* __restrict__ qkv,
                                              uint32_t* __restrict__ ohi,
                                              uint32_t* __restrict__ olo) {
    extern __shared__ __align__(16) float asmem[];
    float (*Ks)[64]  = (float(*)[64])asmem;
    float (*Vs)[64]  = (float(*)[64])(asmem + 64 * 64);
    float* Ssc       = asmem + 2 * 64 * 64;   // [128][65]

    int b = blockIdx.z, h = blockIdx.y, qt = blockIdx.x;
    int t = threadIdx.x;
    int r = t >> 1;            // q-row within block
    int hf = t & 1;            // dim half: 32 floats
    int row = (qt << 7) + r;

    // Q half, pre-scaled by exact 2^-3
    const ulonglong2* qp = (const ulonglong2*)
        (qkv + (size_t)(b * SS + row) * (3 * DD) + DD + h * HDIM + hf * 32);
    ull q2[16];
    ull scv = pack2(0.125f, 0.125f);
    #pragma unroll
    for (int u = 0; u < 8; u++) {
        ulonglong2 v = qp[u];
        q2[2*u]   = mul2(v.x, scv);
        q2[2*u+1] = mul2(v.y, scv);
    }

    ull o2[16];
    #pragma unroll
    for (int u = 0; u < 16; u++) o2[u] = 0ull;
    float m = -1e30f, l = 0.0f;

    int ktmax = ((qt << 7) + 127) >> 6;   // 2*qt + 1
    for (int kt = 0; kt <= ktmax; kt++) {
        __syncthreads();
        #pragma unroll
        for (int i = 0; i < 4; i++) {
            int f = t + (i << 8);
            int rr = f >> 4, c4 = f & 15;
            size_t base = (size_t)(b * SS + (kt << 6) + rr) * (3 * DD) + h * HDIM;
            ((float4*)Ks[rr])[c4] = ((const float4*)(qkv + base))[c4];
            ((float4*)Vs[rr])[c4] = ((const float4*)(qkv + base + 2 * DD))[c4];
        }
        __syncthreads();

        int jmax = row - (kt << 6);
        if (jmax > 63) jmax = 63;

        // phase 1: scores (each lane does its 32-dim half; pair-sum via shfl)
        float tm = -1e30f;
        #pragma unroll 2
        for (int j = 0; j < 64; j++) {
            const ulonglong2* kp = (const ulonglong2*)&Ks[j][hf * 32];
            ull a0 = 0ull, a1 = 0ull, a2 = 0ull, a3 = 0ull;
            #pragma unroll
            for (int u = 0; u < 8; u += 2) {
                ulonglong2 k0 = kp[u], k1 = kp[u + 1];
                fma2(a0, q2[2*u],     k0.x);
                fma2(a1, q2[2*u + 1], k0.y);
                fma2(a2, q2[2*u + 2], k1.x);
                fma2(a3, q2[2*u + 3], k1.y);
            }
            float2 f0 = unpack2(a0), f1 = unpack2(a1);
            float2 f2 = unpack2(a2), f3 = unpack2(a3);
            float part = ((f0.x + f0.y) + (f1.x + f1.y)) + ((f2.x + f2.y) + (f3.x + f3.y));
            float s = part + __shfl_xor_sync(0xffffffffu, part, 1);
            s = (j <= jmax) ? s : -1e30f;
            tm = fmaxf(tm, s);
            if (hf == 0) Ssc[r * 65 + j] = s;
        }

        // phase 2: online softmax update (pair lanes duplicate scalar math)
        float mn = fmaxf(m, tm);
        float c  = __expf(m - mn);
        l *= c;
        ull c2 = pack2(c, c);
        #pragma unroll
        for (int u = 0; u < 16; u++) o2[u] = mul2(o2[u], c2);
        #pragma unroll 2
        for (int j = 0; j < 64; j++) {
            float p = __expf(Ssc[r * 65 + j] - mn);
            l += p;
            ull p2 = pack2(p, p);
            const ulonglong2* vp = (const ulonglong2*)&Vs[j][hf * 32];
            #pragma unroll
            for (int u = 0; u < 8; u++) {
                ulonglong2 vv = vp[u];
                fma2(o2[2*u],   p2, vv.x);
                fma2(o2[2*u+1], p2, vv.y);
            }
        }
        m = mn;
    }

    float inv = 1.0f / l;
    size_t obase = ((size_t)(b * SS + row) * DD + h * HDIM + hf * 32) / 2;
    uint32_t* oh = ohi + obase;
    uint32_t* ol = olo + obase;
    #pragma unroll
    for (int u = 0; u < 16; u++) {
        float2 f = unpack2(o2[u]);
        float vx = f.x * inv, vy = f.y * inv;
        uint32_t hv = bf2(vx, vy);
        float rx = vx - __uint_as_float(hv << 16);
        float ry = vy - __uint_as_float(hv & 0xffff0000u);
        oh[u] = hv;
        ol[u] = bf2(rx, ry);
    }
}

// ---------------------------------------------------------------------------
// Orchestration (graph-capturable: kernel launches only)
// ---------------------------------------------------------------------------
extern "C" void kernel_launch(void* const* d_in, const int* in_sizes, int n_in,
                              void* d_out, int out_size) {
    const int*   idx    = (const int*)  d_in[0];
    const float* wte    = (const float*)d_in[1];
    const float* wpe    = (const float*)d_in[2];
    const float* ln1w   = (const float*)d_in[3];
    const float* ln1b   = (const float*)d_in[4];
    const float* qkvw   = (const float*)d_in[5];
    const float* qkvb   = (const float*)d_in[6];
    const float* projw  = (const float*)d_in[7];
    const float* projb  = (const float*)d_in[8];
    const float* ln2w   = (const float*)d_in[9];
    const float* ln2b   = (const float*)d_in[10];
    const float* fcw    = (const float*)d_in[11];
    const float* fcb    = (const float*)d_in[12];
    const float* cprojw = (const float*)d_in[13];
    const float* cprojb = (const float*)d_in[14];
    const float* lnfw   = (const float*)d_in[15];
    const float* lnfb   = (const float*)d_in[16];
    const float* headw  = (const float*)d_in[17];
    float* out = (float*)d_out;

    float *px, *pq;
    uint32_t *pah, *pal, *pfh, *pfl, *pbh, *pbl;
    cudaGetSymbolAddress((void**)&px,  g_x);
    cudaGetSymbolAddress((void**)&pq,  g_qkv);
    cudaGetSymbolAddress((void**)&pah, g_ah);
    cudaGetSymbolAddress((void**)&pal, g_al);
    cudaGetSymbolAddress((void**)&pfh, g_fh);
    cudaGetSymbolAddress((void**)&pfl, g_fl);
    cudaGetSymbolAddress((void**)&pbh, g_bh);
    cudaGetSymbolAddress((void**)&pbl, g_bl);

    cudaFuncSetAttribute(gemm_bf<0>, cudaFuncAttributeMaxDynamicSharedMemorySize, GEMM_SMEM);
    cudaFuncSetAttribute(gemm_bf<1>, cudaFuncAttributeMaxDynamicSharedMemorySize, GEMM_SMEM);
    cudaFuncSetAttribute(gemm_bf<2>, cudaFuncAttributeMaxDynamicSharedMemorySize, GEMM_SMEM);
    cudaFuncSetAttribute(gemm_bf<3>, cudaFuncAttributeMaxDynamicSharedMemorySize, GEMM_SMEM);
    cudaFuncSetAttribute(attn_k,     cudaFuncAttributeMaxDynamicSharedMemorySize, ATTN_SMEM);

    embed_k<<<MTOK, 256>>>(idx, wte, wpe, px);

    for (int l = 0; l < LL; l++) {
        // --- qkv ---
        ln_k<<<MTOK, 256>>>(px, ln1w + (size_t)l * DD, ln1b + (size_t)l * DD, pah, pal);
        cvt_w<<<3 * DD * DD / 1024, 256>>>(qkvw + (size_t)l * 3 * DD * DD, pbh, pbl, 3 * DD * DD / 4);
        gemm_bf<0><<<dim3(3 * DD / 128, MTOK / 128), 256, GEMM_SMEM>>>(
            (const char*)pah, (const char*)pal, (const char*)pbh, (const char*)pbl,
            qkvb + (size_t)l * 3 * DD, pq, nullptr, nullptr, MTOK, 3 * DD, DD);
        // --- attention ---
        attn_k<<<dim3(SS / 128, HH, BB), 256, ATTN_SMEM>>>(pq, pah, pal);
        // --- proj (+residual) ---
        cvt_w<<<DD * DD / 1024, 256>>>(projw + (size_t)l * DD * DD, pbh, pbl, DD * DD / 4);
        gemm_bf<2><<<dim3(DD / 128, MTOK / 128), 256, GEMM_SMEM>>>(
            (const char*)pah, (const char*)pal, (const char*)pbh, (const char*)pbl,
            projb + (size_t)l * DD, px, nullptr, nullptr, MTOK, DD, DD);
        // --- fc + gelu ---
        ln_k<<<MTOK, 256>>>(px, ln2w + (size_t)l * DD, ln2b + (size_t)l * DD, pah, pal);
        cvt_w<<<4 * DD * DD / 1024, 256>>>(fcw + (size_t)l * 4 * DD * DD, pbh, pbl, 4 * DD * DD / 4);
        gemm_bf<1><<<dim3(4 * DD / 128, MTOK / 128), 256, GEMM_SMEM>>>(
            (const char*)pah, (const char*)pal, (const char*)pbh, (const char*)pbl,
            fcb + (size_t)l * 4 * DD, nullptr, pfh, pfl, MTOK, 4 * DD, DD);
        // --- cproj (+residual) ---
        cvt_w<<<DD * 4 * DD / 1024, 256>>>(cprojw + (size_t)l * DD * 4 * DD, pbh, pbl, DD * 4 * DD / 4);
        gemm_bf<2><<<dim3(DD / 128, MTOK / 128), 256, GEMM_SMEM>>>(
            (const char*)pfh, (const char*)pfl, (const char*)pbh, (const char*)pbl,
            cprojb + (size_t)l * DD, px, nullptr, nullptr, MTOK, DD, 4 * DD);
    }

    ln_k<<<MTOK, 256>>>(px, lnfw, lnfb, pah, pal);
    cvt_w<<<VV * DD / 1024, 256>>>(headw, pbh, pbl, VV * DD / 4);
    gemm_bf<3><<<dim3(VV / 128, MTOK / 128), 256, GEMM_SMEM>>>(
        (const char*)pah, (const char*)pal, (const char*)pbh, (const char*)pbl,
        nullptr, out, nullptr, nullptr, MTOK, VV, DD);
}

// round 12
// speedup vs baseline: 1.2393x; 1.2393x over previous
#include <cuda_runtime.h>
#include <cstdint>
#include <cstddef>

// Problem constants
#define BB 4
#define SS 2048
#define DD 1024
#define HH 16
#define LL 8
#define VV 8192
#define HDIM 64
#define MTOK (BB*SS)   // 8192 tokens

typedef unsigned long long ull;

// ---------------------------------------------------------------------------
// Static device scratch (no allocations allowed)
// ---------------------------------------------------------------------------
__device__ float    g_x  [(size_t)MTOK * DD];           // residual fp32
__device__ float    g_qkv[(size_t)MTOK * 3 * DD];       // qkv fp32
__device__ __align__(16) uint32_t g_ah[(size_t)MTOK * DD / 2];       // act hi bf16
__device__ __align__(16) uint32_t g_al[(size_t)MTOK * DD / 2];       // act lo bf16
__device__ __align__(16) uint32_t g_fh[(size_t)MTOK * 4 * DD / 2];   // fc hi
__device__ __align__(16) uint32_t g_fl[(size_t)MTOK * 4 * DD / 2];   // fc lo
__device__ __align__(16) uint32_t g_bh[(size_t)VV * DD / 2];         // weight hi
__device__ __align__(16) uint32_t g_bl[(size_t)VV * DD / 2];         // weight lo

// ---------------------------------------------------------------------------
// Packed f32x2 helpers
// ---------------------------------------------------------------------------
__device__ __forceinline__ void fma2(ull& d, ull a, ull b) {
    asm("fma.rn.f32x2 %0, %1, %2, %0;" : "+l"(d) : "l"(a), "l"(b));
}
__device__ __forceinline__ ull mul2(ull a, ull b) {
    ull d; asm("mul.rn.f32x2 %0, %1, %2;" : "=l"(d) : "l"(a), "l"(b)); return d;
}
__device__ __forceinline__ ull pack2(float x, float y) {
    ull d; asm("mov.b64 %0, {%1, %2};" : "=l"(d) : "f"(x), "f"(y)); return d;
}
__device__ __forceinline__ float2 unpack2(ull v) {
    float2 r; asm("mov.b64 {%0, %1}, %2;" : "=f"(r.x), "=f"(r.y) : "l"(v)); return r;
}

__device__ __forceinline__ float gelu_f(float x) {
    float z = 0.7978845608028654f * (x + 0.044715f * x * x * x);
    float e = __expf(2.0f * z);
    float th = 1.0f - 2.0f / (e + 1.0f);
    return 0.5f * x * (1.0f + th);
}

// bf16x2 pack: {hi(y) | lo(x)}
__device__ __forceinline__ uint32_t bf2(float lo, float hi) {
    uint32_t r; asm("cvt.rn.bf16x2.f32 %0, %1, %2;" : "=r"(r) : "f"(hi), "f"(lo)); return r;
}

__device__ __forceinline__ uint32_t smem_u32(const void* p) {
    uint32_t a;
    asm("{ .reg .u64 t; cvta.to.shared.u64 t, %1; cvt.u32.u64 %0, t; }" : "=r"(a) : "l"(p));
    return a;
}

// ---------------------------------------------------------------------------
// mma.sync / ldmatrix / cp.async (sm_80-compatible path)
// ---------------------------------------------------------------------------
__device__ __forceinline__ void ldsm4(uint32_t* r, uint32_t addr) {
    asm volatile("ldmatrix.sync.aligned.m8n8.x4.shared.b16 {%0,%1,%2,%3}, [%4];"
        : "=r"(r[0]), "=r"(r[1]), "=r"(r[2]), "=r"(r[3]) : "r"(addr));
}
__device__ __forceinline__ void mma16816(float* c, const uint32_t* a, const uint32_t* b) {
    asm volatile(
        "mma.sync.aligned.m16n8k16.row.col.f32.bf16.bf16.f32 "
        "{%0,%1,%2,%3}, {%4,%5,%6,%7}, {%8,%9}, {%0,%1,%2,%3};"
        : "+f"(c[0]), "+f"(c[1]), "+f"(c[2]), "+f"(c[3])
        : "r"(a[0]), "r"(a[1]), "r"(a[2]), "r"(a[3]), "r"(b[0]), "r"(b[1]));
}
__device__ __forceinline__ void cpa16(uint32_t dst, const void* src) {
    size_t g = __cvta_generic_to_global(src);
    asm volatile("cp.async.cg.shared.global [%0], [%1], 16;" :: "r"(dst), "l"(g) : "memory");
}
#define CPA_COMMIT() asm volatile("cp.async.commit_group;" ::: "memory")
#define CPA_WAIT1()  asm volatile("cp.async.wait_group 1;"  ::: "memory")

// fp32x4 -> bf16 hi (8B) + bf16 lo residual (8B)
__device__ __forceinline__ void cvt_store(void* hi, void* lo, float4 v) {
    uint32_t h0 = bf2(v.x, v.y);
    uint32_t h1 = bf2(v.z, v.w);
    float bx = __uint_as_float(h0 << 16);
    float by = __uint_as_float(h0 & 0xffff0000u);
    float bz = __uint_as_float(h1 << 16);
    float bw = __uint_as_float(h1 & 0xffff0000u);
    uint32_t l0 = bf2(v.x - bx, v.y - by);
    uint32_t l1 = bf2(v.z - bz, v.w - bw);
    *(ull*)hi = ((ull)h1 << 32) | h0;
    *(ull*)lo = ((ull)l1 << 32) | l0;
}

// ---------------------------------------------------------------------------
// Weight conversion: fp32 -> bf16 hi/lo, 4 elems/thread
// ---------------------------------------------------------------------------
__global__ void cvt_w(const float* __restrict__ W, uint32_t* __restrict__ hi,
                      uint32_t* __restrict__ lo, int n4) {
    int i = blockIdx.x * 256 + threadIdx.x;
    if (i >= n4) return;
    float4 v = ((const float4*)W)[i];
    cvt_store((ull*)hi + i, (ull*)lo + i, v);
}

// ---------------------------------------------------------------------------
// Embedding
// ---------------------------------------------------------------------------
__global__ void embed_k(const int* __restrict__ idx, const float* __restrict__ wte,
                        const float* __restrict__ wpe, float* __restrict__ x) {
    int row = blockIdx.x;
    int s   = row & (SS - 1);
    int t   = threadIdx.x;
    int tok = idx[row];
    float4 a = ((const float4*)(wte + (size_t)tok * DD))[t];
    float4 p = ((const float4*)(wpe + (size_t)s * DD))[t];
    ((float4*)(x + (size_t)row * DD))[t] =
        make_float4(a.x + p.x, a.y + p.y, a.z + p.z, a.w + p.w);
}

// ---------------------------------------------------------------------------
// LayerNorm -> split bf16 output (GEMM A operand)
// ---------------------------------------------------------------------------
__global__ void ln_k(const float* __restrict__ x, const float* __restrict__ w,
                     const float* __restrict__ b, uint32_t* __restrict__ ohi,
                     uint32_t* __restrict__ olo) {
    int row = blockIdx.x;
    int t   = threadIdx.x;
    float4 v = ((const float4*)(x + (size_t)row * DD))[t];
    float s = v.x + v.y + v.z + v.w;
    float q = v.x * v.x + v.y * v.y + v.z * v.z + v.w * v.w;
    #pragma unroll
    for (int off = 16; off; off >>= 1) {
        s += __shfl_xor_sync(0xffffffffu, s, off);
        q += __shfl_xor_sync(0xffffffffu, q, off);
    }
    __shared__ float ss[8], sq[8];
    __shared__ float smu, srs;
    int wid = t >> 5;
    if ((t & 31) == 0) { ss[wid] = s; sq[wid] = q; }
    __syncthreads();
    if (t == 0) {
        float S = 0.f, Q = 0.f;
        #pragma unroll
        for (int i = 0; i < 8; i++) { S += ss[i]; Q += sq[i]; }
        float mu  = S * (1.0f / DD);
        float var = Q * (1.0f / DD) - mu * mu;
        smu = mu;
        srs = rsqrtf(var + 1e-5f);
    }
    __syncthreads();
    float mu = smu, r = srs;
    float4 wv = ((const float4*)w)[t];
    float4 bv = ((const float4*)b)[t];
    float4 out;
    out.x = (v.x - mu) * r * wv.x + bv.x;
    out.y = (v.y - mu) * r * wv.y + bv.y;
    out.z = (v.z - mu) * r * wv.z + bv.z;
    out.w = (v.w - mu) * r * wv.w + bv.w;
    size_t i = (size_t)row * (DD / 4) + t;
    cvt_store((ull*)ohi + i, (ull*)olo + i, out);
}

// ---------------------------------------------------------------------------
// Tensor-core NT GEMM on pre-split bf16: C = Ah*Bh + Ah*Bl + Al*Bh.
// CTA 128x128, K-step 32, 3-stage cp.async pipeline (32KB/stage), 2 CTAs/SM.
// Term-major MMA order: same-accumulator reuse distance = 16 MMAs.
// EPI: 0 = fp32 +bias, 1 = gelu(+bias) -> bf16 hi/lo, 2 = fp32 += acc+bias,
//      3 = fp32 plain
// ---------------------------------------------------------------------------
#define STAGE 32768
#define PL_AH 0
#define PL_AL 8192
#define PL_BH 16384
#define PL_BL 24576
#define GEMM_SMEM (3*STAGE)

template<int EPI>
__global__ void __launch_bounds__(256, 2)
gemm_bf(const char* __restrict__ Ah, const char* __restrict__ Al,
        const char* __restrict__ Bh, const char* __restrict__ Bl,
        const float* __restrict__ bias, float* __restrict__ C,
        uint32_t* __restrict__ Chi, uint32_t* __restrict__ Clo,
        int M, int N, int K)
{
    extern __shared__ __align__(16) char sm[];
    int tid  = threadIdx.x;
    int lane = tid & 31;
    int w    = tid >> 5;
    int wm   = w & 1;           // 64-row group
    int wn   = w >> 1;          // 32-col group
    int bn = blockIdx.x << 7, bm = blockIdx.y << 7;
    uint32_t smb = smem_u32(sm);

    float acc[4][4][4];
    #pragma unroll
    for (int i = 0; i < 4; i++)
        #pragma unroll
        for (int j = 0; j < 4; j++)
            #pragma unroll
            for (int r = 0; r < 4; r++) acc[i][j][r] = 0.f;

    int nk = K >> 5;
    int lr = tid >> 1;            // 0..127 tile row
    int q0 = (tid & 1) << 1;      // chunk base 0 or 2
    size_t arow = (size_t)(bm + lr) * K;
    size_t brow = (size_t)(bn + lr) * K;
    int sw = (lr >> 1) & 3;

    auto fill = [&](int slot, int ks) {
        int kc = ks << 5;
        uint32_t sb = smb + slot * STAGE + lr * 64;
        #pragma unroll
        for (int c = 0; c < 2; c++) {
            int q = q0 + c;
            uint32_t d = sb + ((q ^ sw) << 4);
            size_t ao = (arow + kc + q * 8) * 2;
            size_t bo = (brow + kc + q * 8) * 2;
            cpa16(d + PL_AH, Ah + ao);
            cpa16(d + PL_AL, Al + ao);
            cpa16(d + PL_BH, Bh + bo);
            cpa16(d + PL_BL, Bl + bo);
        }
    };
    fill(0, 0); CPA_COMMIT();
    fill(1, 1); CPA_COMMIT();

    for (int t = 0; t < nk; t++) {
        CPA_WAIT1();
        __syncthreads();
        if (t + 2 < nk) fill((t + 2) % 3, t + 2);
        CPA_COMMIT();

        uint32_t base = smb + (t % 3) * STAGE;
        #pragma unroll
        for (int kh = 0; kh < 2; kh++) {
            int cch = kh * 2 + (lane >> 4);
            uint32_t ahf[4][4], alf[4][4];
            #pragma unroll
            for (int mi = 0; mi < 4; mi++) {
                int row = wm * 64 + mi * 16 + (lane & 15);
                uint32_t ad = base + row * 64 + ((cch ^ ((row >> 1) & 3)) << 4);
                ldsm4(ahf[mi], ad + PL_AH);
                ldsm4(alf[mi], ad + PL_AL);
            }
            uint32_t bhq[2][4], blq[2][4];
            #pragma unroll
            for (int np = 0; np < 2; np++) {
                int row = wn * 32 + np * 16 + (lane & 15);
                uint32_t bd = base + row * 64 + ((cch ^ ((row >> 1) & 3)) << 4);
                ldsm4(bhq[np], bd + PL_BH);
                ldsm4(blq[np], bd + PL_BL);
            }
            uint32_t bhf[4][2], blf[4][2];
            #pragma unroll
            for (int np = 0; np < 2; np++)
                #pragma unroll
                for (int sdx = 0; sdx < 2; sdx++) {
                    bhf[np * 2 + sdx][0] = bhq[np][sdx];
                    bhf[np * 2 + sdx][1] = bhq[np][sdx + 2];
                    blf[np * 2 + sdx][0] = blq[np][sdx];
                    blf[np * 2 + sdx][1] = blq[np][sdx + 2];
                }
            // Term-major issue order: 16 independent MMAs between any
            // same-accumulator reuse (hides HMMA latency within one warp).
            #pragma unroll
            for (int mi = 0; mi < 4; mi++)
                #pragma unroll
                for (int ni = 0; ni < 4; ni++)
                    mma16816(acc[mi][ni], ahf[mi], bhf[ni]);
            #pragma unroll
            for (int mi = 0; mi < 4; mi++)
                #pragma unroll
                for (int ni = 0; ni < 4; ni++)
                    mma16816(acc[mi][ni], ahf[mi], blf[ni]);
            #pragma unroll
            for (int mi = 0; mi < 4; mi++)
                #pragma unroll
                for (int ni = 0; ni < 4; ni++)
                    mma16816(acc[mi][ni], alf[mi], bhf[ni]);
        }
    }

    // Epilogue: thread owns rows (r0, r0+8) x cols (c, c+1) per (mi,ni) tile
    int rbase = bm + wm * 64 + (lane >> 2);
    int cbase = bn + wn * 32 + ((lane & 3) << 1);
    #pragma unroll
    for (int mi = 0; mi < 4; mi++) {
        #pragma unroll
        for (int ni = 0; ni < 4; ni++) {
            float* cc = acc[mi][ni];
            int col  = cbase + ni * 8;
            int row0 = rbase + mi * 16;
            float b0 = 0.f, b1 = 0.f;
            if (EPI != 3) { b0 = bias[col]; b1 = bias[col + 1]; }
            #pragma unroll
            for (int half = 0; half < 2; half++) {
                int row = row0 + half * 8;
                float vx = cc[half * 2] + b0;
                float vy = cc[half * 2 + 1] + b1;
                if (EPI == 1) {
                    vx = gelu_f(vx); vy = gelu_f(vy);
                    uint32_t hv = bf2(vx, vy);
                    float rx = vx - __uint_as_float(hv << 16);
                    float ry = vy - __uint_as_float(hv & 0xffff0000u);
                    uint32_t lv = bf2(rx, ry);
                    size_t idx = ((size_t)row * N + col) >> 1;
                    Chi[idx] = hv;
                    Clo[idx] = lv;
                } else {
                    float* cp = C + (size_t)row * N + col;
                    if (EPI == 2) {
                        float2 o = *(const float2*)cp;
                        vx += o.x; vy += o.y;
                    }
                    *(float2*)cp = make_float2(vx, vy);
                }
            }
        }
    }
}

// ---------------------------------------------------------------------------
// Flash attention (causal). 128 q-rows/block, 1 thread/row, f32x2 math.
// Output written as split bf16 (proj GEMM A operand). [R6 known-good version]
// ---------------------------------------------------------------------------
#define ATTN_SMEM ((64*64*2 + 128*65) * 4)

__global__ __launch_bounds__(128) void attn_k(const float* __restrict__ qkv,
                                              uint32_t* __restrict__ ohi,
                                              uint32_t* __restrict__ olo) {
    extern __shared__ __align__(16) float asmem[];
    float (*Ks)[64]  = (float(*)[64])asmem;
    float (*Vs)[64]  = (float(*)[64])(asmem + 64 * 64);
    float* Ssc       = asmem + 2 * 64 * 64;   // [128][65]

    int b = blockIdx.z, h = blockIdx.y, qt = blockIdx.x;
    int t = threadIdx.x;
    int row = (qt << 7) + t;

    const ulonglong2* qp =
        (const ulonglong2*)(qkv + (size_t)(b * SS + row) * (3 * DD) + DD + h * HDIM);
    ull q2[32];
    ull sc = pack2(0.125f, 0.125f);
    #pragma unroll
    for (int u = 0; u < 16; u++) {
        ulonglong2 v = qp[u];
        q2[2*u]   = mul2(v.x, sc);
        q2[2*u+1] = mul2(v.y, sc);
    }

    ull o2[32];
    #pragma unroll
    for (int u = 0; u < 32; u++) o2[u] = 0ull;
    float m = -1e30f, l = 0.0f;

    int ktmax = ((qt << 7) + 127) >> 6;   // 2*qt + 1
    for (int kt = 0; kt <= ktmax; kt++) {
        __syncthreads();
        #pragma unroll
        for (int i = 0; i < 8; i++) {
            int f = t + (i << 7);
            int r = f >> 4, c4 = f & 15;
            size_t base = (size_t)(b * SS + (kt << 6) + r) * (3 * DD) + h * HDIM;
            ((float4*)Ks[r])[c4] = ((const float4*)(qkv + base))[c4];
            ((float4*)Vs[r])[c4] = ((const float4*)(qkv + base + 2 * DD))[c4];
        }
        __syncthreads();

        int jmax = row - (kt << 6);
        if (jmax > 63) jmax = 63;

        float tm = -1e30f;
        #pragma unroll 2
        for (int j = 0; j < 64; j++) {
            const ulonglong2* kp = (const ulonglong2*)Ks[j];
            ull a0 = 0ull, a1 = 0ull, a2 = 0ull, a3 = 0ull;
            #pragma unroll
            for (int u = 0; u < 16; u += 2) {
                ulonglong2 k0 = kp[u], k1 = kp[u + 1];
                fma2(a0, q2[2*u],     k0.x);
                fma2(a1, q2[2*u + 1], k0.y);
                fma2(a2, q2[2*u + 2], k1.x);
                fma2(a3, q2[2*u + 3], k1.y);
            }
            float2 f0 = unpack2(a0), f1 = unpack2(a1);
            float2 f2 = unpack2(a2), f3 = unpack2(a3);
            float s = ((f0.x + f0.y) + (f1.x + f1.y)) + ((f2.x + f2.y) + (f3.x + f3.y));
            s = (j <= jmax) ? s : -1e30f;
            tm = fmaxf(tm, s);
            Ssc[t * 65 + j] = s;
        }

        float mn = fmaxf(m, tm);
        float c  = __expf(m - mn);
        l *= c;
        ull c2 = pack2(c, c);
        #pragma unroll
        for (int u = 0; u < 32; u++) o2[u] = mul2(o2[u], c2);
        #pragma unroll 2
        for (int j = 0; j < 64; j++) {
            float p = __expf(Ssc[t * 65 + j] - mn);
            l += p;
            ull p2 = pack2(p, p);
            const ulonglong2* vp = (const ulonglong2*)Vs[j];
            #pragma unroll
            for (int u = 0; u < 16; u++) {
                ulonglong2 vv = vp[u];
                fma2(o2[2*u],   p2, vv.x);
                fma2(o2[2*u+1], p2, vv.y);
            }
        }
        m = mn;
    }

    float inv = 1.0f / l;
    uint32_t* oh = ohi + ((size_t)(b * SS + row) * DD + h * HDIM) / 2;
    uint32_t* ol = olo + ((size_t)(b * SS + row) * DD + h * HDIM) / 2;
    #pragma unroll
    for (int u = 0; u < 32; u++) {
        float2 f = unpack2(o2[u]);
        float vx = f.x * inv, vy = f.y * inv;
        uint32_t hv = bf2(vx, vy);
        float rx = vx - __uint_as_float(hv << 16);
        float ry = vy - __uint_as_float(hv & 0xffff0000u);
        oh[u] = hv;
        ol[u] = bf2(rx, ry);
    }
}

// ---------------------------------------------------------------------------
// Orchestration (graph-capturable: kernel launches only)
// ---------------------------------------------------------------------------
extern "C" void kernel_launch(void* const* d_in, const int* in_sizes, int n_in,
                              void* d_out, int out_size) {
    const int*   idx    = (const int*)  d_in[0];
    const float* wte    = (const float*)d_in[1];
    const float* wpe    = (const float*)d_in[2];
    const float* ln1w   = (const float*)d_in[3];
    const float* ln1b   = (const float*)d_in[4];
    const float* qkvw   = (const float*)d_in[5];
    const float* qkvb   = (const float*)d_in[6];
    const float* projw  = (const float*)d_in[7];
    const float* projb  = (const float*)d_in[8];
    const float* ln2w   = (const float*)d_in[9];
    const float* ln2b   = (const float*)d_in[10];
    const float* fcw    = (const float*)d_in[11];
    const float* fcb    = (const float*)d_in[12];
    const float* cprojw = (const float*)d_in[13];
    const float* cprojb = (const float*)d_in[14];
    const float* lnfw   = (const float*)d_in[15];
    const float* lnfb   = (const float*)d_in[16];
    const float* headw  = (const float*)d_in[17];
    float* out = (float*)d_out;

    float *px, *pq;
    uint32_t *pah, *pal, *pfh, *pfl, *pbh, *pbl;
    cudaGetSymbolAddress((void**)&px,  g_x);
    cudaGetSymbolAddress((void**)&pq,  g_qkv);
    cudaGetSymbolAddress((void**)&pah, g_ah);
    cudaGetSymbolAddress((void**)&pal, g_al);
    cudaGetSymbolAddress((void**)&pfh, g_fh);
    cudaGetSymbolAddress((void**)&pfl, g_fl);
    cudaGetSymbolAddress((void**)&pbh, g_bh);
    cudaGetSymbolAddress((void**)&pbl, g_bl);

    cudaFuncSetAttribute(gemm_bf<0>, cudaFuncAttributeMaxDynamicSharedMemorySize, GEMM_SMEM);
    cudaFuncSetAttribute(gemm_bf<1>, cudaFuncAttributeMaxDynamicSharedMemorySize, GEMM_SMEM);
    cudaFuncSetAttribute(gemm_bf<2>, cudaFuncAttributeMaxDynamicSharedMemorySize, GEMM_SMEM);
    cudaFuncSetAttribute(gemm_bf<3>, cudaFuncAttributeMaxDynamicSharedMemorySize, GEMM_SMEM);
    cudaFuncSetAttribute(attn_k,     cudaFuncAttributeMaxDynamicSharedMemorySize, ATTN_SMEM);

    embed_k<<<MTOK, 256>>>(idx, wte, wpe, px);

    for (int l = 0; l < LL; l++) {
        // --- qkv ---
        ln_k<<<MTOK, 256>>>(px, ln1w + (size_t)l * DD, ln1b + (size_t)l * DD, pah, pal);
        cvt_w<<<3 * DD * DD / 1024, 256>>>(qkvw + (size_t)l * 3 * DD * DD, pbh, pbl, 3 * DD * DD / 4);
        gemm_bf<0><<<dim3(3 * DD / 128, MTOK / 128), 256, GEMM_SMEM>>>(
            (const char*)pah, (const char*)pal, (const char*)pbh, (const char*)pbl,
            qkvb + (size_t)l * 3 * DD, pq, nullptr, nullptr, MTOK, 3 * DD, DD);
        // --- attention ---
        attn_k<<<dim3(SS / 128, HH, BB), 128, ATTN_SMEM>>>(pq, pah, pal);
        // --- proj (+residual) ---
        cvt_w<<<DD * DD / 1024, 256>>>(projw + (size_t)l * DD * DD, pbh, pbl, DD * DD / 4);
        gemm_bf<2><<<dim3(DD / 128, MTOK / 128), 256, GEMM_SMEM>>>(
            (const char*)pah, (const char*)pal, (const char*)pbh, (const char*)pbl,
            projb + (size_t)l * DD, px, nullptr, nullptr, MTOK, DD, DD);
        // --- fc + gelu ---
        ln_k<<<MTOK, 256>>>(px, ln2w + (size_t)l * DD, ln2b + (size_t)l * DD, pah, pal);
        cvt_w<<<4 * DD * DD / 1024, 256>>>(fcw + (size_t)l * 4 * DD * DD, pbh, pbl, 4 * DD * DD / 4);
        gemm_bf<1><<<dim3(4 * DD / 128, MTOK / 128), 256, GEMM_SMEM>>>(
            (const char*)pah, (const char*)pal, (const char*)pbh, (const char*)pbl,
            fcb + (size_t)l * 4 * DD, nullptr, pfh, pfl, MTOK, 4 * DD, DD);
        // --- cproj (+residual) ---
        cvt_w<<<DD * 4 * DD / 1024, 256>>>(cprojw + (size_t)l * DD * 4 * DD, pbh, pbl, DD * 4 * DD / 4);
        gemm_bf<2><<<dim3(DD / 128, MTOK / 128), 256, GEMM_SMEM>>>(
            (const char*)pfh, (const char*)pfl, (const char*)pbh, (const char*)pbl,
            cprojb + (size_t)l * DD, px, nullptr, nullptr, MTOK, DD, 4 * DD);
    }

    ln_k<<<MTOK, 256>>>(px, lnfw, lnfb, pah, pal);
    cvt_w<<<VV * DD / 1024, 256>>>(headw, pbh, pbl, VV * DD / 4);
    gemm_bf<3><<<dim3(VV / 128, MTOK / 128), 256, GEMM_SMEM>>>(
        (const char*)pah, (const char*)pal, (const char*)pbh, (const char*)pbl,
        nullptr, out, nullptr, nullptr, MTOK, VV, DD);
}

// round 13
// speedup vs baseline: 1.7189x; 1.3870x over previous
#include <cuda_runtime.h>
#include <cstdint>
#include <cstddef>

// Problem constants
#define BB 4
#define SS 2048
#define DD 1024
#define HH 16
#define LL 8
#define VV 8192
#define HDIM 64
#define MTOK (BB*SS)   // 8192 tokens

typedef unsigned long long ull;

// ---------------------------------------------------------------------------
// Static device scratch (no allocations allowed)
// ---------------------------------------------------------------------------
__device__ float    g_x  [(size_t)MTOK * DD];           // residual fp32
__device__ float    g_qkv[(size_t)MTOK * 3 * DD];       // qkv fp32
__device__ __align__(16) uint32_t g_ah[(size_t)MTOK * DD / 2];       // act hi bf16
__device__ __align__(16) uint32_t g_al[(size_t)MTOK * DD / 2];       // act lo bf16
__device__ __align__(16) uint32_t g_fh[(size_t)MTOK * 4 * DD / 2];   // fc hi
__device__ __align__(16) uint32_t g_fl[(size_t)MTOK * 4 * DD / 2];   // fc lo
__device__ __align__(16) uint32_t g_bh[(size_t)VV * DD / 2];         // weight hi
__device__ __align__(16) uint32_t g_bl[(size_t)VV * DD / 2];         // weight lo

// ---------------------------------------------------------------------------
// Helpers
// ---------------------------------------------------------------------------
__device__ __forceinline__ float gelu_f(float x) {
    float z = 0.7978845608028654f * (x + 0.044715f * x * x * x);
    float e = __expf(2.0f * z);
    float th = 1.0f - 2.0f / (e + 1.0f);
    return 0.5f * x * (1.0f + th);
}

// bf16x2 pack: {hi(y) | lo(x)}
__device__ __forceinline__ uint32_t bf2(float lo, float hi) {
    uint32_t r; asm("cvt.rn.bf16x2.f32 %0, %1, %2;" : "=r"(r) : "f"(hi), "f"(lo)); return r;
}

// split (x,y) -> bf16x2 hi + bf16x2 residual
__device__ __forceinline__ void split2(float x, float y, uint32_t& hi, uint32_t& lo) {
    hi = bf2(x, y);
    float rx = x - __uint_as_float(hi << 16);
    float ry = y - __uint_as_float(hi & 0xffff0000u);
    lo = bf2(rx, ry);
}

__device__ __forceinline__ uint32_t smem_u32(const void* p) {
    uint32_t a;
    asm("{ .reg .u64 t; cvta.to.shared.u64 t, %1; cvt.u32.u64 %0, t; }" : "=r"(a) : "l"(p));
    return a;
}

// ---------------------------------------------------------------------------
// mma.sync / ldmatrix / cp.async (sm_80-compatible path)
// ---------------------------------------------------------------------------
__device__ __forceinline__ void ldsm4(uint32_t* r, uint32_t addr) {
    asm volatile("ldmatrix.sync.aligned.m8n8.x4.shared.b16 {%0,%1,%2,%3}, [%4];"
        : "=r"(r[0]), "=r"(r[1]), "=r"(r[2]), "=r"(r[3]) : "r"(addr));
}
__device__ __forceinline__ void mma16816(float* c, const uint32_t* a, const uint32_t* b) {
    asm volatile(
        "mma.sync.aligned.m16n8k16.row.col.f32.bf16.bf16.f32 "
        "{%0,%1,%2,%3}, {%4,%5,%6,%7}, {%8,%9}, {%0,%1,%2,%3};"
        : "+f"(c[0]), "+f"(c[1]), "+f"(c[2]), "+f"(c[3])
        : "r"(a[0]), "r"(a[1]), "r"(a[2]), "r"(a[3]), "r"(b[0]), "r"(b[1]));
}
__device__ __forceinline__ void cpa16(uint32_t dst, const void* src) {
    size_t g = __cvta_generic_to_global(src);
    asm volatile("cp.async.cg.shared.global [%0], [%1], 16;" :: "r"(dst), "l"(g) : "memory");
}
#define CPA_COMMIT() asm volatile("cp.async.commit_group;" ::: "memory")
#define CPA_WAIT1()  asm volatile("cp.async.wait_group 1;"  ::: "memory")

// fp32x4 -> bf16 hi (8B) + bf16 lo residual (8B)
__device__ __forceinline__ void cvt_store(void* hi, void* lo, float4 v) {
    uint32_t h0 = bf2(v.x, v.y);
    uint32_t h1 = bf2(v.z, v.w);
    float bx = __uint_as_float(h0 << 16);
    float by = __uint_as_float(h0 & 0xffff0000u);
    float bz = __uint_as_float(h1 << 16);
    float bw = __uint_as_float(h1 & 0xffff0000u);
    uint32_t l0 = bf2(v.x - bx, v.y - by);
    uint32_t l1 = bf2(v.z - bz, v.w - bw);
    *(ull*)hi = ((ull)h1 << 32) | h0;
    *(ull*)lo = ((ull)l1 << 32) | l0;
}

// ---------------------------------------------------------------------------
// Weight conversion: fp32 -> bf16 hi/lo, 4 elems/thread
// ---------------------------------------------------------------------------
__global__ void cvt_w(const float* __restrict__ W, uint32_t* __restrict__ hi,
                      uint32_t* __restrict__ lo, int n4) {
    int i = blockIdx.x * 256 + threadIdx.x;
    if (i >= n4) return;
    float4 v = ((const float4*)W)[i];
    cvt_store((ull*)hi + i, (ull*)lo + i, v);
}

// ---------------------------------------------------------------------------
// Embedding
// ---------------------------------------------------------------------------
__global__ void embed_k(const int* __restrict__ idx, const float* __restrict__ wte,
                        const float* __restrict__ wpe, float* __restrict__ x) {
    int row = blockIdx.x;
    int s   = row & (SS - 1);
    int t   = threadIdx.x;
    int tok = idx[row];
    float4 a = ((const float4*)(wte + (size_t)tok * DD))[t];
    float4 p = ((const float4*)(wpe + (size_t)s * DD))[t];
    ((float4*)(x + (size_t)row * DD))[t] =
        make_float4(a.x + p.x, a.y + p.y, a.z + p.z, a.w + p.w);
}

// ---------------------------------------------------------------------------
// LayerNorm -> split bf16 output (GEMM A operand)
// ---------------------------------------------------------------------------
__global__ void ln_k(const float* __restrict__ x, const float* __restrict__ w,
                     const float* __restrict__ b, uint32_t* __restrict__ ohi,
                     uint32_t* __restrict__ olo) {
    int row = blockIdx.x;
    int t   = threadIdx.x;
    float4 v = ((const float4*)(x + (size_t)row * DD))[t];
    float s = v.x + v.y + v.z + v.w;
    float q = v.x * v.x + v.y * v.y + v.z * v.z + v.w * v.w;
    #pragma unroll
    for (int off = 16; off; off >>= 1) {
        s += __shfl_xor_sync(0xffffffffu, s, off);
        q += __shfl_xor_sync(0xffffffffu, q, off);
    }
    __shared__ float ss[8], sq[8];
    __shared__ float smu, srs;
    int wid = t >> 5;
    if ((t & 31) == 0) { ss[wid] = s; sq[wid] = q; }
    __syncthreads();
    if (t == 0) {
        float S = 0.f, Q = 0.f;
        #pragma unroll
        for (int i = 0; i < 8; i++) { S += ss[i]; Q += sq[i]; }
        float mu  = S * (1.0f / DD);
        float var = Q * (1.0f / DD) - mu * mu;
        smu = mu;
        srs = rsqrtf(var + 1e-5f);
    }
    __syncthreads();
    float mu = smu, r = srs;
    float4 wv = ((const float4*)w)[t];
    float4 bv = ((const float4*)b)[t];
    float4 out;
    out.x = (v.x - mu) * r * wv.x + bv.x;
    out.y = (v.y - mu) * r * wv.y + bv.y;
    out.z = (v.z - mu) * r * wv.z + bv.z;
    out.w = (v.w - mu) * r * wv.w + bv.w;
    size_t i = (size_t)row * (DD / 4) + t;
    cvt_store((ull*)ohi + i, (ull*)olo + i, out);
}

// ---------------------------------------------------------------------------
// Tensor-core NT GEMM on pre-split bf16 (unchanged from R8; at HMMA floor)
// ---------------------------------------------------------------------------
#define STAGE 32768
#define PL_AH 0
#define PL_AL 8192
#define PL_BH 16384
#define PL_BL 24576
#define GEMM_SMEM (3*STAGE)

template<int EPI>
__global__ void __launch_bounds__(256, 2)
gemm_bf(const char* __restrict__ Ah, const char* __restrict__ Al,
        const char* __restrict__ Bh, const char* __restrict__ Bl,
        const float* __restrict__ bias, float* __restrict__ C,
        uint32_t* __restrict__ Chi, uint32_t* __restrict__ Clo,
        int M, int N, int K)
{
    extern __shared__ __align__(16) char sm[];
    int tid  = threadIdx.x;
    int lane = tid & 31;
    int w    = tid >> 5;
    int wm   = w & 1;
    int wn   = w >> 1;
    int bn = blockIdx.x << 7, bm = blockIdx.y << 7;
    uint32_t smb = smem_u32(sm);

    float acc[4][4][4];
    #pragma unroll
    for (int i = 0; i < 4; i++)
        #pragma unroll
        for (int j = 0; j < 4; j++)
            #pragma unroll
            for (int r = 0; r < 4; r++) acc[i][j][r] = 0.f;

    int nk = K >> 5;
    int lr = tid >> 1;
    int q0 = (tid & 1) << 1;
    size_t arow = (size_t)(bm + lr) * K;
    size_t brow = (size_t)(bn + lr) * K;
    int sw = (lr >> 1) & 3;

    auto fill = [&](int slot, int ks) {
        int kc = ks << 5;
        uint32_t sb = smb + slot * STAGE + lr * 64;
        #pragma unroll
        for (int c = 0; c < 2; c++) {
            int q = q0 + c;
            uint32_t d = sb + ((q ^ sw) << 4);
            size_t ao = (arow + kc + q * 8) * 2;
            size_t bo = (brow + kc + q * 8) * 2;
            cpa16(d + PL_AH, Ah + ao);
            cpa16(d + PL_AL, Al + ao);
            cpa16(d + PL_BH, Bh + bo);
            cpa16(d + PL_BL, Bl + bo);
        }
    };
    fill(0, 0); CPA_COMMIT();
    fill(1, 1); CPA_COMMIT();

    for (int t = 0; t < nk; t++) {
        CPA_WAIT1();
        __syncthreads();
        if (t + 2 < nk) fill((t + 2) % 3, t + 2);
        CPA_COMMIT();

        uint32_t base = smb + (t % 3) * STAGE;
        #pragma unroll
        for (int kh = 0; kh < 2; kh++) {
            int cch = kh * 2 + (lane >> 4);
            uint32_t ahf[4][4], alf[4][4];
            #pragma unroll
            for (int mi = 0; mi < 4; mi++) {
                int row = wm * 64 + mi * 16 + (lane & 15);
                uint32_t ad = base + row * 64 + ((cch ^ ((row >> 1) & 3)) << 4);
                ldsm4(ahf[mi], ad + PL_AH);
                ldsm4(alf[mi], ad + PL_AL);
            }
            uint32_t bhq[2][4], blq[2][4];
            #pragma unroll
            for (int np = 0; np < 2; np++) {
                int row = wn * 32 + np * 16 + (lane & 15);
                uint32_t bd = base + row * 64 + ((cch ^ ((row >> 1) & 3)) << 4);
                ldsm4(bhq[np], bd + PL_BH);
                ldsm4(blq[np], bd + PL_BL);
            }
            uint32_t bhf[4][2], blf[4][2];
            #pragma unroll
            for (int np = 0; np < 2; np++)
                #pragma unroll
                for (int sdx = 0; sdx < 2; sdx++) {
                    bhf[np * 2 + sdx][0] = bhq[np][sdx];
                    bhf[np * 2 + sdx][1] = bhq[np][sdx + 2];
                    blf[np * 2 + sdx][0] = blq[np][sdx];
                    blf[np * 2 + sdx][1] = blq[np][sdx + 2];
                }
            #pragma unroll
            for (int mi = 0; mi < 4; mi++)
                #pragma unroll
                for (int ni = 0; ni < 4; ni++)
                    mma16816(acc[mi][ni], ahf[mi], bhf[ni]);
            #pragma unroll
            for (int mi = 0; mi < 4; mi++)
                #pragma unroll
                for (int ni = 0; ni < 4; ni++)
                    mma16816(acc[mi][ni], ahf[mi], blf[ni]);
            #pragma unroll
            for (int mi = 0; mi < 4; mi++)
                #pragma unroll
                for (int ni = 0; ni < 4; ni++)
                    mma16816(acc[mi][ni], alf[mi], bhf[ni]);
        }
    }

    int rbase = bm + wm * 64 + (lane >> 2);
    int cbase = bn + wn * 32 + ((lane & 3) << 1);
    #pragma unroll
    for (int mi = 0; mi < 4; mi++) {
        #pragma unroll
        for (int ni = 0; ni < 4; ni++) {
            float* cc = acc[mi][ni];
            int col  = cbase + ni * 8;
            int row0 = rbase + mi * 16;
            float b0 = 0.f, b1 = 0.f;
            if (EPI != 3) { b0 = bias[col]; b1 = bias[col + 1]; }
            #pragma unroll
            for (int half = 0; half < 2; half++) {
                int row = row0 + half * 8;
                float vx = cc[half * 2] + b0;
                float vy = cc[half * 2 + 1] + b1;
                if (EPI == 1) {
                    vx = gelu_f(vx); vy = gelu_f(vy);
                    uint32_t hv, lv;
                    split2(vx, vy, hv, lv);
                    size_t idx = ((size_t)row * N + col) >> 1;
                    Chi[idx] = hv;
                    Clo[idx] = lv;
                } else {
                    float* cp = C + (size_t)row * N + col;
                    if (EPI == 2) {
                        float2 o = *(const float2*)cp;
                        vx += o.x; vy += o.y;
                    }
                    *(float2*)cp = make_float2(vx, vy);
                }
            }
        }
    }
}

// ---------------------------------------------------------------------------
// Tensor-core flash attention (causal). Block = 64 q-rows, 128 threads
// (4 warps x m16). K/V tiles 64x64 converted fp32 -> bf16 hi/lo in smem;
// V stored transposed (Vt[d][s]) so all ldmatrix use the GEMM-proven
// non-trans addressing. Scores & PV use 3-term bf16 split; online softmax
// on C-fragments; output written as split bf16 (proj GEMM A operand).
// ---------------------------------------------------------------------------
__global__ __launch_bounds__(128) void attn_k(const float* __restrict__ qkv,
                                              uint32_t* __restrict__ ohi,
                                              uint32_t* __restrict__ olo) {
    __shared__ __align__(16) char KsH[8192];
    __shared__ __align__(16) char KsL[8192];
    __shared__ __align__(16) char VtH[8192];
    __shared__ __align__(16) char VtL[8192];

    int b = blockIdx.z, h = blockIdx.y, qt = blockIdx.x;
    int t = threadIdx.x, lane = t & 31, wid = t >> 5;
    int qb = qt << 6;
    const float* hb = qkv + (size_t)b * SS * (3 * DD) + h * HDIM;

    uint32_t ksh = smem_u32(KsH), ksl = smem_u32(KsL);
    uint32_t vth = smem_u32(VtH), vtl = smem_u32(VtL);

    // ---- load Q tile (64 x 64), scaled by exact 1/8, into Ks planes ----
    {
        int row = t >> 1;
        int ch0 = (t & 1) * 4;
        const float* src = hb + (size_t)(qb + row) * (3 * DD) + DD + ch0 * 8;
        #pragma unroll
        for (int c = 0; c < 4; c++) {
            float4 va = ((const float4*)src)[c * 2];
            float4 vb = ((const float4*)src)[c * 2 + 1];
            va.x *= 0.125f; va.y *= 0.125f; va.z *= 0.125f; va.w *= 0.125f;
            vb.x *= 0.125f; vb.y *= 0.125f; vb.z *= 0.125f; vb.w *= 0.125f;
            int off = row * 128 + (((ch0 + c) ^ (row & 7)) << 4);
            cvt_store(KsH + off,     KsL + off,     va);
            cvt_store(KsH + off + 8, KsL + off + 8, vb);
        }
    }
    __syncthreads();

    // Q A-fragments (per warp: m16, 4 k16 chunks, hi/lo planes)
    uint32_t qfh[4][4], qfl[4][4];
    #pragma unroll
    for (int kc = 0; kc < 4; kc++) {
        int row = wid * 16 + (lane & 15);
        int c = kc * 2 + (lane >> 4);
        uint32_t off = (uint32_t)(row * 128 + ((c ^ (row & 7)) << 4));
        ldsm4(qfh[kc], ksh + off);
        ldsm4(qfl[kc], ksl + off);
    }

    float o[8][4];
    #pragma unroll
    for (int i = 0; i < 8; i++)
        #pragma unroll
        for (int j = 0; j < 4; j++) o[i][j] = 0.f;
    float m0 = -1e30f, m1 = -1e30f, l0 = 0.f, l1 = 0.f;

    for (int kt = 0; kt <= qt; kt++) {
        __syncthreads();
        // ---- K tile (64 seq x 64 d) ----
        {
            int row = t >> 1;
            int ch0 = (t & 1) * 4;
            const float* src = hb + (size_t)((kt << 6) + row) * (3 * DD) + ch0 * 8;
            #pragma unroll
            for (int c = 0; c < 4; c++) {
                float4 va = ((const float4*)src)[c * 2];
                float4 vb = ((const float4*)src)[c * 2 + 1];
                int off = row * 128 + (((ch0 + c) ^ (row & 7)) << 4);
                cvt_store(KsH + off,     KsL + off,     va);
                cvt_store(KsH + off + 8, KsL + off + 8, vb);
            }
        }
        // ---- V tile, transposed store: Vt[d][s], pair of seq in one u32 ----
        {
            int s0 = (lane) * 2;            // seq pair base (warp-local lane)
            int db = wid * 16;              // 16 d-rows per warp
            const float* v0 = hb + (size_t)((kt << 6) + s0) * (3 * DD) + 2 * DD + db;
            const float* v1 = v0 + 3 * DD;
            #pragma unroll
            for (int dd = 0; dd < 16; dd += 4) {
                float4 x0 = *(const float4*)(v0 + dd);
                float4 x1 = *(const float4*)(v1 + dd);
                const float* a0 = (const float*)&x0;
                const float* a1 = (const float*)&x1;
                #pragma unroll
                for (int e = 0; e < 4; e++) {
                    int d = db + dd + e;
                    uint32_t hv, lv;
                    split2(a0[e], a1[e], hv, lv);
                    int off = d * 128 + (((s0 >> 3) ^ (d & 7)) << 4) + (s0 & 7) * 2;
                    *(uint32_t*)(VtH + off) = hv;
                    *(uint32_t*)(VtL + off) = lv;
                }
            }
        }
        __syncthreads();

        // ---- S = Q K^T  (3-term bf16) ----
        float s[8][4];
        #pragma unroll
        for (int i = 0; i < 8; i++)
            #pragma unroll
            for (int j = 0; j < 4; j++) s[i][j] = 0.f;

        #pragma unroll
        for (int kc = 0; kc < 4; kc++) {
            uint32_t kbh[8][2], kbl[8][2];
            #pragma unroll
            for (int np = 0; np < 4; np++) {
                int row = np * 16 + (lane & 15);
                int c = kc * 2 + (lane >> 4);
                uint32_t off = (uint32_t)(row * 128 + ((c ^ (row & 7)) << 4));
                uint32_t qq[4];
                ldsm4(qq, ksh + off);
                kbh[np*2][0] = qq[0]; kbh[np*2][1] = qq[2];
                kbh[np*2+1][0] = qq[1]; kbh[np*2+1][1] = qq[3];
                ldsm4(qq, ksl + off);
                kbl[np*2][0] = qq[0]; kbl[np*2][1] = qq[2];
                kbl[np*2+1][0] = qq[1]; kbl[np*2+1][1] = qq[3];
            }
            #pragma unroll
            for (int nt = 0; nt < 8; nt++) mma16816(s[nt], qfh[kc], kbh[nt]);
            #pragma unroll
            for (int nt = 0; nt < 8; nt++) mma16816(s[nt], qfh[kc], kbl[nt]);
            #pragma unroll
            for (int nt = 0; nt < 8; nt++) mma16816(s[nt], qfl[kc], kbh[nt]);
        }

        // ---- causal mask (diagonal tile only) ----
        if (kt == qt) {
            int cb = (lane & 3) * 2;
            int r0 = wid * 16 + (lane >> 2), r1 = r0 + 8;
            #pragma unroll
            for (int nt = 0; nt < 8; nt++) {
                int c0 = nt * 8 + cb;
                if (c0     > r0) s[nt][0] = -1e30f;
                if (c0 + 1 > r0) s[nt][1] = -1e30f;
                if (c0     > r1) s[nt][2] = -1e30f;
                if (c0 + 1 > r1) s[nt][3] = -1e30f;
            }
        }

        // ---- online softmax (rows r0 = lane>>2, r1 = r0+8 of warp m16) ----
        float mx0 = -1e30f, mx1 = -1e30f;
        #pragma unroll
        for (int nt = 0; nt < 8; nt++) {
            mx0 = fmaxf(mx0, fmaxf(s[nt][0], s[nt][1]));
            mx1 = fmaxf(mx1, fmaxf(s[nt][2], s[nt][3]));
        }
        mx0 = fmaxf(mx0, __shfl_xor_sync(0xffffffffu, mx0, 1));
        mx0 = fmaxf(mx0, __shfl_xor_sync(0xffffffffu, mx0, 2));
        mx1 = fmaxf(mx1, __shfl_xor_sync(0xffffffffu, mx1, 1));
        mx1 = fmaxf(mx1, __shfl_xor_sync(0xffffffffu, mx1, 2));
        float mn0 = fmaxf(m0, mx0), mn1 = fmaxf(m1, mx1);
        float sc0 = __expf(m0 - mn0), sc1 = __expf(m1 - mn1);
        m0 = mn0; m1 = mn1;
        float su0 = 0.f, su1 = 0.f;
        #pragma unroll
        for (int nt = 0; nt < 8; nt++) {
            s[nt][0] = __expf(s[nt][0] - mn0); su0 += s[nt][0];
            s[nt][1] = __expf(s[nt][1] - mn0); su0 += s[nt][1];
            s[nt][2] = __expf(s[nt][2] - mn1); su1 += s[nt][2];
            s[nt][3] = __expf(s[nt][3] - mn1); su1 += s[nt][3];
        }
        su0 += __shfl_xor_sync(0xffffffffu, su0, 1);
        su0 += __shfl_xor_sync(0xffffffffu, su0, 2);
        su1 += __shfl_xor_sync(0xffffffffu, su1, 1);
        su1 += __shfl_xor_sync(0xffffffffu, su1, 2);
        l0 = l0 * sc0 + su0;
        l1 = l1 * sc1 + su1;
        #pragma unroll
        for (int nt = 0; nt < 8; nt++) {
            o[nt][0] *= sc0; o[nt][1] *= sc0;
            o[nt][2] *= sc1; o[nt][3] *= sc1;
        }

        // ---- O += P V  (P C-frags -> A-frags, 3-term bf16) ----
        #pragma unroll
        for (int kc = 0; kc < 4; kc++) {
            uint32_t pah[4], pal[4];
            split2(s[2*kc][0],   s[2*kc][1],   pah[0], pal[0]);
            split2(s[2*kc][2],   s[2*kc][3],   pah[1], pal[1]);
            split2(s[2*kc+1][0], s[2*kc+1][1], pah[2], pal[2]);
            split2(s[2*kc+1][2], s[2*kc+1][3], pah[3], pal[3]);
            uint32_t vbh[8][2], vbl[8][2];
            #pragma unroll
            for (int np = 0; np < 4; np++) {
                int row = np * 16 + (lane & 15);
                int c = kc * 2 + (lane >> 4);
                uint32_t off = (uint32_t)(row * 128 + ((c ^ (row & 7)) << 4));
                uint32_t qq[4];
                ldsm4(qq, vth + off);
                vbh[np*2][0] = qq[0]; vbh[np*2][1] = qq[2];
                vbh[np*2+1][0] = qq[1]; vbh[np*2+1][1] = qq[3];
                ldsm4(qq, vtl + off);
                vbl[np*2][0] = qq[0]; vbl[np*2][1] = qq[2];
                vbl[np*2+1][0] = qq[1]; vbl[np*2+1][1] = qq[3];
            }
            #pragma unroll
            for (int nt = 0; nt < 8; nt++) mma16816(o[nt], pah, vbh[nt]);
            #pragma unroll
            for (int nt = 0; nt < 8; nt++) mma16816(o[nt], pah, vbl[nt]);
            #pragma unroll
            for (int nt = 0; nt < 8; nt++) mma16816(o[nt], pal, vbh[nt]);
        }
    }

    // ---- normalize + write split bf16 ----
    float i0 = 1.0f / l0, i1 = 1.0f / l1;
    int r0 = qb + wid * 16 + (lane >> 2);
    size_t tok0 = (size_t)b * SS + r0;
    size_t base0 = (tok0 * DD + h * HDIM + (lane & 3) * 2) >> 1;
    size_t base1 = base0 + (size_t)4 * DD;   // row + 8
    #pragma unroll
    for (int nt = 0; nt < 8; nt++) {
        uint32_t hv, lv;
        split2(o[nt][0] * i0, o[nt][1] * i0, hv, lv);
        ohi[base0 + nt * 4] = hv;
        olo[base0 + nt * 4] = lv;
        split2(o[nt][2] * i1, o[nt][3] * i1, hv, lv);
        ohi[base1 + nt * 4] = hv;
        olo[base1 + nt * 4] = lv;
    }
}

// ---------------------------------------------------------------------------
// Orchestration (graph-capturable: kernel launches only)
// ---------------------------------------------------------------------------
extern "C" void kernel_launch(void* const* d_in, const int* in_sizes, int n_in,
                              void* d_out, int out_size) {
    const int*   idx    = (const int*)  d_in[0];
    const float* wte    = (const float*)d_in[1];
    const float* wpe    = (const float*)d_in[2];
    const float* ln1w   = (const float*)d_in[3];
    const float* ln1b   = (const float*)d_in[4];
    const float* qkvw   = (const float*)d_in[5];
    const float* qkvb   = (const float*)d_in[6];
    const float* projw  = (const float*)d_in[7];
    const float* projb  = (const float*)d_in[8];
    const float* ln2w   = (const float*)d_in[9];
    const float* ln2b   = (const float*)d_in[10];
    const float* fcw    = (const float*)d_in[11];
    const float* fcb    = (const float*)d_in[12];
    const float* cprojw = (const float*)d_in[13];
    const float* cprojb = (const float*)d_in[14];
    const float* lnfw   = (const float*)d_in[15];
    const float* lnfb   = (const float*)d_in[16];
    const float* headw  = (const float*)d_in[17];
    float* out = (float*)d_out;

    float *px, *pq;
    uint32_t *pah, *pal, *pfh, *pfl, *pbh, *pbl;
    cudaGetSymbolAddress((void**)&px,  g_x);
    cudaGetSymbolAddress((void**)&pq,  g_qkv);
    cudaGetSymbolAddress((void**)&pah, g_ah);
    cudaGetSymbolAddress((void**)&pal, g_al);
    cudaGetSymbolAddress((void**)&pfh, g_fh);
    cudaGetSymbolAddress((void**)&pfl, g_fl);
    cudaGetSymbolAddress((void**)&pbh, g_bh);
    cudaGetSymbolAddress((void**)&pbl, g_bl);

    cudaFuncSetAttribute(gemm_bf<0>, cudaFuncAttributeMaxDynamicSharedMemorySize, GEMM_SMEM);
    cudaFuncSetAttribute(gemm_bf<1>, cudaFuncAttributeMaxDynamicSharedMemorySize, GEMM_SMEM);
    cudaFuncSetAttribute(gemm_bf<2>, cudaFuncAttributeMaxDynamicSharedMemorySize, GEMM_SMEM);
    cudaFuncSetAttribute(gemm_bf<3>, cudaFuncAttributeMaxDynamicSharedMemorySize, GEMM_SMEM);

    embed_k<<<MTOK, 256>>>(idx, wte, wpe, px);

    for (int l = 0; l < LL; l++) {
        // --- qkv ---
        ln_k<<<MTOK, 256>>>(px, ln1w + (size_t)l * DD, ln1b + (size_t)l * DD, pah, pal);
        cvt_w<<<3 * DD * DD / 1024, 256>>>(qkvw + (size_t)l * 3 * DD * DD, pbh, pbl, 3 * DD * DD / 4);
        gemm_bf<0><<<dim3(3 * DD / 128, MTOK / 128), 256, GEMM_SMEM>>>(
            (const char*)pah, (const char*)pal, (const char*)pbh, (const char*)pbl,
            qkvb + (size_t)l * 3 * DD, pq, nullptr, nullptr, MTOK, 3 * DD, DD);
        // --- attention (tensor-core flash) ---
        attn_k<<<dim3(SS / 64, HH, BB), 128>>>(pq, pah, pal);
        // --- proj (+residual) ---
        cvt_w<<<DD * DD / 1024, 256>>>(projw + (size_t)l * DD * DD, pbh, pbl, DD * DD / 4);
        gemm_bf<2><<<dim3(DD / 128, MTOK / 128), 256, GEMM_SMEM>>>(
            (const char*)pah, (const char*)pal, (const char*)pbh, (const char*)pbl,
            projb + (size_t)l * DD, px, nullptr, nullptr, MTOK, DD, DD);
        // --- fc + gelu ---
        ln_k<<<MTOK, 256>>>(px, ln2w + (size_t)l * DD, ln2b + (size_t)l * DD, pah, pal);
        cvt_w<<<4 * DD * DD / 1024, 256>>>(fcw + (size_t)l * 4 * DD * DD, pbh, pbl, 4 * DD * DD / 4);
        gemm_bf<1><<<dim3(4 * DD / 128, MTOK / 128), 256, GEMM_SMEM>>>(
            (const char*)pah, (const char*)pal, (const char*)pbh, (const char*)pbl,
            fcb + (size_t)l * 4 * DD, nullptr, pfh, pfl, MTOK, 4 * DD, DD);
        // --- cproj (+residual) ---
        cvt_w<<<DD * 4 * DD / 1024, 256>>>(cprojw + (size_t)l * DD * 4 * DD, pbh, pbl, DD * 4 * DD / 4);
        gemm_bf<2><<<dim3(DD / 128, MTOK / 128), 256, GEMM_SMEM>>>(
            (const char*)pfh, (const char*)pfl, (const char*)pbh, (const char*)pbl,
            cprojb + (size_t)l * DD, px, nullptr, nullptr, MTOK, DD, 4 * DD);
    }

    ln_k<<<MTOK, 256>>>(px, lnfw, lnfb, pah, pal);
    cvt_w<<<VV * DD / 1024, 256>>>(headw, pbh, pbl, VV * DD / 4);
    gemm_bf<3><<<dim3(VV / 128, MTOK / 128), 256, GEMM_SMEM>>>(
        (const char*)pah, (const char*)pal, (const char*)pbh, (const char*)pbl,
        nullptr, out, nullptr, nullptr, MTOK, VV, DD);
}

// round 14
// speedup vs baseline: 2.2397x; 1.3030x over previous
#include <cuda_runtime.h>
#include <cuda_fp16.h>
#include <cstdint>
#include <cstddef>

// Problem constants
#define BB 4
#define SS 2048
#define DD 1024
#define HH 16
#define LL 8
#define VV 8192
#define HDIM 64
#define MTOK (BB*SS)   // 8192 tokens

typedef unsigned long long ull;

// ---------------------------------------------------------------------------
// Static device scratch (no allocations allowed)
// ---------------------------------------------------------------------------
__device__ float    g_x  [(size_t)MTOK * DD];           // residual fp32
__device__ float    g_qkv[(size_t)MTOK * 3 * DD];       // qkv fp32
__device__ __align__(16) uint32_t g_ah[(size_t)MTOK * DD / 2];       // act hi fp16
__device__ __align__(16) uint32_t g_al[(size_t)MTOK * DD / 2];       // act lo fp16
__device__ __align__(16) uint32_t g_fh[(size_t)MTOK * 4 * DD / 2];   // fc hi
__device__ __align__(16) uint32_t g_fl[(size_t)MTOK * 4 * DD / 2];   // fc lo
__device__ __align__(16) uint32_t g_bh[(size_t)VV * DD / 2];         // weight hi fp16

// ---------------------------------------------------------------------------
// Helpers
// ---------------------------------------------------------------------------
__device__ __forceinline__ float gelu_f(float x) {
    float z = 0.7978845608028654f * (x + 0.044715f * x * x * x);
    float e = __expf(2.0f * z);
    float th = 1.0f - 2.0f / (e + 1.0f);
    return 0.5f * x * (1.0f + th);
}

// bf16x2 pack: {hi(y) | lo(x)}  (attention-internal only)
__device__ __forceinline__ uint32_t bf2(float lo, float hi) {
    uint32_t r; asm("cvt.rn.bf16x2.f32 %0, %1, %2;" : "=r"(r) : "f"(hi), "f"(lo)); return r;
}
// bf16 split (attention-internal)
__device__ __forceinline__ void split2(float x, float y, uint32_t& hi, uint32_t& lo) {
    hi = bf2(x, y);
    float rx = x - __uint_as_float(hi << 16);
    float ry = y - __uint_as_float(hi & 0xffff0000u);
    lo = bf2(rx, ry);
}

// fp16x2 pack (x low, y high) + residual split
__device__ __forceinline__ uint32_t h2pack(float x, float y) {
    __half2 h = __floats2half2_rn(x, y);
    return *(uint32_t*)&h;
}
__device__ __forceinline__ void split2h(float x, float y, uint32_t& hi, uint32_t& lo) {
    __half2 h = __floats2half2_rn(x, y);
    hi = *(uint32_t*)&h;
    float2 f = __half22float2(h);
    __half2 l = __floats2half2_rn(x - f.x, y - f.y);
    lo = *(uint32_t*)&l;
}

__device__ __forceinline__ uint32_t smem_u32(const void* p) {
    uint32_t a;
    asm("{ .reg .u64 t; cvta.to.shared.u64 t, %1; cvt.u32.u64 %0, t; }" : "=r"(a) : "l"(p));
    return a;
}

// ---------------------------------------------------------------------------
// mma.sync / ldmatrix / cp.async (sm_80-compatible path)
// ---------------------------------------------------------------------------
__device__ __forceinline__ void ldsm4(uint32_t* r, uint32_t addr) {
    asm volatile("ldmatrix.sync.aligned.m8n8.x4.shared.b16 {%0,%1,%2,%3}, [%4];"
        : "=r"(r[0]), "=r"(r[1]), "=r"(r[2]), "=r"(r[3]) : "r"(addr));
}
// bf16 variant (attention)
__device__ __forceinline__ void mma16816(float* c, const uint32_t* a, const uint32_t* b) {
    asm volatile(
        "mma.sync.aligned.m16n8k16.row.col.f32.bf16.bf16.f32 "
        "{%0,%1,%2,%3}, {%4,%5,%6,%7}, {%8,%9}, {%0,%1,%2,%3};"
        : "+f"(c[0]), "+f"(c[1]), "+f"(c[2]), "+f"(c[3])
        : "r"(a[0]), "r"(a[1]), "r"(a[2]), "r"(a[3]), "r"(b[0]), "r"(b[1]));
}
// fp16 variant (GEMM)
__device__ __forceinline__ void mma16816h(float* c, const uint32_t* a, const uint32_t* b) {
    asm volatile(
        "mma.sync.aligned.m16n8k16.row.col.f32.f16.f16.f32 "
        "{%0,%1,%2,%3}, {%4,%5,%6,%7}, {%8,%9}, {%0,%1,%2,%3};"
        : "+f"(c[0]), "+f"(c[1]), "+f"(c[2]), "+f"(c[3])
        : "r"(a[0]), "r"(a[1]), "r"(a[2]), "r"(a[3]), "r"(b[0]), "r"(b[1]));
}
__device__ __forceinline__ void cpa16(uint32_t dst, const void* src) {
    size_t g = __cvta_generic_to_global(src);
    asm volatile("cp.async.cg.shared.global [%0], [%1], 16;" :: "r"(dst), "l"(g) : "memory");
}
#define CPA_COMMIT() asm volatile("cp.async.commit_group;" ::: "memory")
#define CPA_WAIT1()  asm volatile("cp.async.wait_group 1;"  ::: "memory")

// fp32x4 -> bf16 hi/lo (attention-internal tiles)
__device__ __forceinline__ void cvt_store(void* hi, void* lo, float4 v) {
    uint32_t h0 = bf2(v.x, v.y);
    uint32_t h1 = bf2(v.z, v.w);
    float bx = __uint_as_float(h0 << 16);
    float by = __uint_as_float(h0 & 0xffff0000u);
    float bz = __uint_as_float(h1 << 16);
    float bw = __uint_as_float(h1 & 0xffff0000u);
    uint32_t l0 = bf2(v.x - bx, v.y - by);
    uint32_t l1 = bf2(v.z - bz, v.w - bw);
    *(ull*)hi = ((ull)h1 << 32) | h0;
    *(ull*)lo = ((ull)l1 << 32) | l0;
}

// fp32x4 -> fp16 hi (8B) + fp16 lo residual (8B)
__device__ __forceinline__ void cvt_storeh(void* hi, void* lo, float4 v) {
    uint32_t h0, l0, h1, l1;
    split2h(v.x, v.y, h0, l0);
    split2h(v.z, v.w, h1, l1);
    *(ull*)hi = ((ull)h1 << 32) | h0;
    *(ull*)lo = ((ull)l1 << 32) | l0;
}

// ---------------------------------------------------------------------------
// Weight conversion: fp32 -> fp16 hi only (B operand is single-plane)
// ---------------------------------------------------------------------------
__global__ void cvt_w(const float* __restrict__ W, uint32_t* __restrict__ hi, int n4) {
    int i = blockIdx.x * 256 + threadIdx.x;
    if (i >= n4) return;
    float4 v = ((const float4*)W)[i];
    uint32_t h0 = h2pack(v.x, v.y);
    uint32_t h1 = h2pack(v.z, v.w);
    ((ull*)hi)[i] = ((ull)h1 << 32) | h0;
}

// ---------------------------------------------------------------------------
// Embedding
// ---------------------------------------------------------------------------
__global__ void embed_k(const int* __restrict__ idx, const float* __restrict__ wte,
                        const float* __restrict__ wpe, float* __restrict__ x) {
    int row = blockIdx.x;
    int s   = row & (SS - 1);
    int t   = threadIdx.x;
    int tok = idx[row];
    float4 a = ((const float4*)(wte + (size_t)tok * DD))[t];
    float4 p = ((const float4*)(wpe + (size_t)s * DD))[t];
    ((float4*)(x + (size_t)row * DD))[t] =
        make_float4(a.x + p.x, a.y + p.y, a.z + p.z, a.w + p.w);
}

// ---------------------------------------------------------------------------
// LayerNorm -> split fp16 output (GEMM A operand)
// ---------------------------------------------------------------------------
__global__ void ln_k(const float* __restrict__ x, const float* __restrict__ w,
                     const float* __restrict__ b, uint32_t* __restrict__ ohi,
                     uint32_t* __restrict__ olo) {
    int row = blockIdx.x;
    int t   = threadIdx.x;
    float4 v = ((const float4*)(x + (size_t)row * DD))[t];
    float s = v.x + v.y + v.z + v.w;
    float q = v.x * v.x + v.y * v.y + v.z * v.z + v.w * v.w;
    #pragma unroll
    for (int off = 16; off; off >>= 1) {
        s += __shfl_xor_sync(0xffffffffu, s, off);
        q += __shfl_xor_sync(0xffffffffu, q, off);
    }
    __shared__ float ss[8], sq[8];
    __shared__ float smu, srs;
    int wid = t >> 5;
    if ((t & 31) == 0) { ss[wid] = s; sq[wid] = q; }
    __syncthreads();
    if (t == 0) {
        float S = 0.f, Q = 0.f;
        #pragma unroll
        for (int i = 0; i < 8; i++) { S += ss[i]; Q += sq[i]; }
        float mu  = S * (1.0f / DD);
        float var = Q * (1.0f / DD) - mu * mu;
        smu = mu;
        srs = rsqrtf(var + 1e-5f);
    }
    __syncthreads();
    float mu = smu, r = srs;
    float4 wv = ((const float4*)w)[t];
    float4 bv = ((const float4*)b)[t];
    float4 out;
    out.x = (v.x - mu) * r * wv.x + bv.x;
    out.y = (v.y - mu) * r * wv.y + bv.y;
    out.z = (v.z - mu) * r * wv.z + bv.z;
    out.w = (v.w - mu) * r * wv.w + bv.w;
    size_t i = (size_t)row * (DD / 4) + t;
    cvt_storeh((ull*)ohi + i, (ull*)olo + i, out);
}

// ---------------------------------------------------------------------------
// Tensor-core NT GEMM, fp16 two-term: C = (Ah+Al) * Bh^T.
// A split fp16 hi/lo (22-bit), B single fp16 plane (12-bit weights).
// CTA 128x128, K-step 32, 3-stage cp.async (24KB/stage), 2 CTAs/SM.
// EPI: 0 = fp32 +bias, 1 = gelu(+bias) -> fp16 hi/lo, 2 = fp32 += acc+bias,
//      3 = fp32 plain
// ---------------------------------------------------------------------------
#define STAGE 24576
#define PL_AH 0
#define PL_AL 8192
#define PL_BH 16384
#define GEMM_SMEM (3*STAGE)

template<int EPI>
__global__ void __launch_bounds__(256, 2)
gemm_bf(const char* __restrict__ Ah, const char* __restrict__ Al,
        const char* __restrict__ Bh,
        const float* __restrict__ bias, float* __restrict__ C,
        uint32_t* __restrict__ Chi, uint32_t* __restrict__ Clo,
        int M, int N, int K)
{
    extern __shared__ __align__(16) char sm[];
    int tid  = threadIdx.x;
    int lane = tid & 31;
    int w    = tid >> 5;
    int wm   = w & 1;
    int wn   = w >> 1;
    int bn = blockIdx.x << 7, bm = blockIdx.y << 7;
    uint32_t smb = smem_u32(sm);

    float acc[4][4][4];
    #pragma unroll
    for (int i = 0; i < 4; i++)
        #pragma unroll
        for (int j = 0; j < 4; j++)
            #pragma unroll
            for (int r = 0; r < 4; r++) acc[i][j][r] = 0.f;

    int nk = K >> 5;
    int lr = tid >> 1;
    int q0 = (tid & 1) << 1;
    size_t arow = (size_t)(bm + lr) * K;
    size_t brow = (size_t)(bn + lr) * K;
    int sw = (lr >> 1) & 3;

    auto fill = [&](int slot, int ks) {
        int kc = ks << 5;
        uint32_t sb = smb + slot * STAGE + lr * 64;
        #pragma unroll
        for (int c = 0; c < 2; c++) {
            int q = q0 + c;
            uint32_t d = sb + ((q ^ sw) << 4);
            size_t ao = (arow + kc + q * 8) * 2;
            size_t bo = (brow + kc + q * 8) * 2;
            cpa16(d + PL_AH, Ah + ao);
            cpa16(d + PL_AL, Al + ao);
            cpa16(d + PL_BH, Bh + bo);
        }
    };
    fill(0, 0); CPA_COMMIT();
    fill(1, 1); CPA_COMMIT();

    for (int t = 0; t < nk; t++) {
        CPA_WAIT1();
        __syncthreads();
        if (t + 2 < nk) fill((t + 2) % 3, t + 2);
        CPA_COMMIT();

        uint32_t base = smb + (t % 3) * STAGE;
        #pragma unroll
        for (int kh = 0; kh < 2; kh++) {
            int cch = kh * 2 + (lane >> 4);
            uint32_t ahf[4][4], alf[4][4];
            #pragma unroll
            for (int mi = 0; mi < 4; mi++) {
                int row = wm * 64 + mi * 16 + (lane & 15);
                uint32_t ad = base + row * 64 + ((cch ^ ((row >> 1) & 3)) << 4);
                ldsm4(ahf[mi], ad + PL_AH);
                ldsm4(alf[mi], ad + PL_AL);
            }
            uint32_t bhq[2][4];
            #pragma unroll
            for (int np = 0; np < 2; np++) {
                int row = wn * 32 + np * 16 + (lane & 15);
                uint32_t bd = base + row * 64 + ((cch ^ ((row >> 1) & 3)) << 4);
                ldsm4(bhq[np], bd + PL_BH);
            }
            uint32_t bhf[4][2];
            #pragma unroll
            for (int np = 0; np < 2; np++)
                #pragma unroll
                for (int sdx = 0; sdx < 2; sdx++) {
                    bhf[np * 2 + sdx][0] = bhq[np][sdx];
                    bhf[np * 2 + sdx][1] = bhq[np][sdx + 2];
                }
            #pragma unroll
            for (int mi = 0; mi < 4; mi++)
                #pragma unroll
                for (int ni = 0; ni < 4; ni++)
                    mma16816h(acc[mi][ni], ahf[mi], bhf[ni]);
            #pragma unroll
            for (int mi = 0; mi < 4; mi++)
                #pragma unroll
                for (int ni = 0; ni < 4; ni++)
                    mma16816h(acc[mi][ni], alf[mi], bhf[ni]);
        }
    }

    int rbase = bm + wm * 64 + (lane >> 2);
    int cbase = bn + wn * 32 + ((lane & 3) << 1);
    #pragma unroll
    for (int mi = 0; mi < 4; mi++) {
        #pragma unroll
        for (int ni = 0; ni < 4; ni++) {
            float* cc = acc[mi][ni];
            int col  = cbase + ni * 8;
            int row0 = rbase + mi * 16;
            float b0 = 0.f, b1 = 0.f;
            if (EPI != 3) { b0 = bias[col]; b1 = bias[col + 1]; }
            #pragma unroll
            for (int half = 0; half < 2; half++) {
                int row = row0 + half * 8;
                float vx = cc[half * 2] + b0;
                float vy = cc[half * 2 + 1] + b1;
                if (EPI == 1) {
                    vx = gelu_f(vx); vy = gelu_f(vy);
                    uint32_t hv, lv;
                    split2h(vx, vy, hv, lv);
                    size_t idx = ((size_t)row * N + col) >> 1;
                    Chi[idx] = hv;
                    Clo[idx] = lv;
                } else {
                    float* cp = C + (size_t)row * N + col;
                    if (EPI == 2) {
                        float2 o = *(const float2*)cp;
                        vx += o.x; vy += o.y;
                    }
                    *(float2*)cp = make_float2(vx, vy);
                }
            }
        }
    }
}

// ---------------------------------------------------------------------------
// Tensor-core flash attention (causal) — internal bf16x3 (unchanged from R12);
// output now written as split fp16 (proj GEMM A operand).
// ---------------------------------------------------------------------------
__global__ __launch_bounds__(128) void attn_k(const float* __restrict__ qkv,
                                              uint32_t* __restrict__ ohi,
                                              uint32_t* __restrict__ olo) {
    __shared__ __align__(16) char KsH[8192];
    __shared__ __align__(16) char KsL[8192];
    __shared__ __align__(16) char VtH[8192];
    __shared__ __align__(16) char VtL[8192];

    int b = blockIdx.z, h = blockIdx.y, qt = blockIdx.x;
    int t = threadIdx.x, lane = t & 31, wid = t >> 5;
    int qb = qt << 6;
    const float* hb = qkv + (size_t)b * SS * (3 * DD) + h * HDIM;

    uint32_t ksh = smem_u32(KsH), ksl = smem_u32(KsL);
    uint32_t vth = smem_u32(VtH), vtl = smem_u32(VtL);

    // ---- load Q tile (64 x 64), scaled by exact 1/8 ----
    {
        int row = t >> 1;
        int ch0 = (t & 1) * 4;
        const float* src = hb + (size_t)(qb + row) * (3 * DD) + DD + ch0 * 8;
        #pragma unroll
        for (int c = 0; c < 4; c++) {
            float4 va = ((const float4*)src)[c * 2];
            float4 vb = ((const float4*)src)[c * 2 + 1];
            va.x *= 0.125f; va.y *= 0.125f; va.z *= 0.125f; va.w *= 0.125f;
            vb.x *= 0.125f; vb.y *= 0.125f; vb.z *= 0.125f; vb.w *= 0.125f;
            int off = row * 128 + (((ch0 + c) ^ (row & 7)) << 4);
            cvt_store(KsH + off,     KsL + off,     va);
            cvt_store(KsH + off + 8, KsL + off + 8, vb);
        }
    }
    __syncthreads();

    uint32_t qfh[4][4], qfl[4][4];
    #pragma unroll
    for (int kc = 0; kc < 4; kc++) {
        int row = wid * 16 + (lane & 15);
        int c = kc * 2 + (lane >> 4);
        uint32_t off = (uint32_t)(row * 128 + ((c ^ (row & 7)) << 4));
        ldsm4(qfh[kc], ksh + off);
        ldsm4(qfl[kc], ksl + off);
    }

    float o[8][4];
    #pragma unroll
    for (int i = 0; i < 8; i++)
        #pragma unroll
        for (int j = 0; j < 4; j++) o[i][j] = 0.f;
    float m0 = -1e30f, m1 = -1e30f, l0 = 0.f, l1 = 0.f;

    for (int kt = 0; kt <= qt; kt++) {
        __syncthreads();
        {
            int row = t >> 1;
            int ch0 = (t & 1) * 4;
            const float* src = hb + (size_t)((kt << 6) + row) * (3 * DD) + ch0 * 8;
            #pragma unroll
            for (int c = 0; c < 4; c++) {
                float4 va = ((const float4*)src)[c * 2];
                float4 vb = ((const float4*)src)[c * 2 + 1];
                int off = row * 128 + (((ch0 + c) ^ (row & 7)) << 4);
                cvt_store(KsH + off,     KsL + off,     va);
                cvt_store(KsH + off + 8, KsL + off + 8, vb);
            }
        }
        {
            int s0 = (lane) * 2;
            int db = wid * 16;
            const float* v0 = hb + (size_t)((kt << 6) + s0) * (3 * DD) + 2 * DD + db;
            const float* v1 = v0 + 3 * DD;
            #pragma unroll
            for (int dd = 0; dd < 16; dd += 4) {
                float4 x0 = *(const float4*)(v0 + dd);
                float4 x1 = *(const float4*)(v1 + dd);
                const float* a0 = (const float*)&x0;
                const float* a1 = (const float*)&x1;
                #pragma unroll
                for (int e = 0; e < 4; e++) {
                    int d = db + dd + e;
                    uint32_t hv, lv;
                    split2(a0[e], a1[e], hv, lv);
                    int off = d * 128 + (((s0 >> 3) ^ (d & 7)) << 4) + (s0 & 7) * 2;
                    *(uint32_t*)(VtH + off) = hv;
                    *(uint32_t*)(VtL + off) = lv;
                }
            }
        }
        __syncthreads();

        float s[8][4];
        #pragma unroll
        for (int i = 0; i < 8; i++)
            #pragma unroll
            for (int j = 0; j < 4; j++) s[i][j] = 0.f;

        #pragma unroll
        for (int kc = 0; kc < 4; kc++) {
            uint32_t kbh[8][2], kbl[8][2];
            #pragma unroll
            for (int np = 0; np < 4; np++) {
                int row = np * 16 + (lane & 15);
                int c = kc * 2 + (lane >> 4);
                uint32_t off = (uint32_t)(row * 128 + ((c ^ (row & 7)) << 4));
                uint32_t qq[4];
                ldsm4(qq, ksh + off);
                kbh[np*2][0] = qq[0]; kbh[np*2][1] = qq[2];
                kbh[np*2+1][0] = qq[1]; kbh[np*2+1][1] = qq[3];
                ldsm4(qq, ksl + off);
                kbl[np*2][0] = qq[0]; kbl[np*2][1] = qq[2];
                kbl[np*2+1][0] = qq[1]; kbl[np*2+1][1] = qq[3];
            }
            #pragma unroll
            for (int nt = 0; nt < 8; nt++) mma16816(s[nt], qfh[kc], kbh[nt]);
            #pragma unroll
            for (int nt = 0; nt < 8; nt++) mma16816(s[nt], qfh[kc], kbl[nt]);
            #pragma unroll
            for (int nt = 0; nt < 8; nt++) mma16816(s[nt], qfl[kc], kbh[nt]);
        }

        if (kt == qt) {
            int cb = (lane & 3) * 2;
            int r0 = wid * 16 + (lane >> 2), r1 = r0 + 8;
            #pragma unroll
            for (int nt = 0; nt < 8; nt++) {
                int c0 = nt * 8 + cb;
                if (c0     > r0) s[nt][0] = -1e30f;
                if (c0 + 1 > r0) s[nt][1] = -1e30f;
                if (c0     > r1) s[nt][2] = -1e30f;
                if (c0 + 1 > r1) s[nt][3] = -1e30f;
            }
        }

        float mx0 = -1e30f, mx1 = -1e30f;
        #pragma unroll
        for (int nt = 0; nt < 8; nt++) {
            mx0 = fmaxf(mx0, fmaxf(s[nt][0], s[nt][1]));
            mx1 = fmaxf(mx1, fmaxf(s[nt][2], s[nt][3]));
        }
        mx0 = fmaxf(mx0, __shfl_xor_sync(0xffffffffu, mx0, 1));
        mx0 = fmaxf(mx0, __shfl_xor_sync(0xffffffffu, mx0, 2));
        mx1 = fmaxf(mx1, __shfl_xor_sync(0xffffffffu, mx1, 1));
        mx1 = fmaxf(mx1, __shfl_xor_sync(0xffffffffu, mx1, 2));
        float mn0 = fmaxf(m0, mx0), mn1 = fmaxf(m1, mx1);
        float sc0 = __expf(m0 - mn0), sc1 = __expf(m1 - mn1);
        m0 = mn0; m1 = mn1;
        float su0 = 0.f, su1 = 0.f;
        #pragma unroll
        for (int nt = 0; nt < 8; nt++) {
            s[nt][0] = __expf(s[nt][0] - mn0); su0 += s[nt][0];
            s[nt][1] = __expf(s[nt][1] - mn0); su0 += s[nt][1];
            s[nt][2] = __expf(s[nt][2] - mn1); su1 += s[nt][2];
            s[nt][3] = __expf(s[nt][3] - mn1); su1 += s[nt][3];
        }
        su0 += __shfl_xor_sync(0xffffffffu, su0, 1);
        su0 += __shfl_xor_sync(0xffffffffu, su0, 2);
        su1 += __shfl_xor_sync(0xffffffffu, su1, 1);
        su1 += __shfl_xor_sync(0xffffffffu, su1, 2);
        l0 = l0 * sc0 + su0;
        l1 = l1 * sc1 + su1;
        #pragma unroll
        for (int nt = 0; nt < 8; nt++) {
            o[nt][0] *= sc0; o[nt][1] *= sc0;
            o[nt][2] *= sc1; o[nt][3] *= sc1;
        }

        #pragma unroll
        for (int kc = 0; kc < 4; kc++) {
            uint32_t pah[4], pal[4];
            split2(s[2*kc][0],   s[2*kc][1],   pah[0], pal[0]);
            split2(s[2*kc][2],   s[2*kc][3],   pah[1], pal[1]);
            split2(s[2*kc+1][0], s[2*kc+1][1], pah[2], pal[2]);
            split2(s[2*kc+1][2], s[2*kc+1][3], pah[3], pal[3]);
            uint32_t vbh[8][2], vbl[8][2];
            #pragma unroll
            for (int np = 0; np < 4; np++) {
                int row = np * 16 + (lane & 15);
                int c = kc * 2 + (lane >> 4);
                uint32_t off = (uint32_t)(row * 128 + ((c ^ (row & 7)) << 4));
                uint32_t qq[4];
                ldsm4(qq, vth + off);
                vbh[np*2][0] = qq[0]; vbh[np*2][1] = qq[2];
                vbh[np*2+1][0] = qq[1]; vbh[np*2+1][1] = qq[3];
                ldsm4(qq, vtl + off);
                vbl[np*2][0] = qq[0]; vbl[np*2][1] = qq[2];
                vbl[np*2+1][0] = qq[1]; vbl[np*2+1][1] = qq[3];
            }
            #pragma unroll
            for (int nt = 0; nt < 8; nt++) mma16816(o[nt], pah, vbh[nt]);
            #pragma unroll
            for (int nt = 0; nt < 8; nt++) mma16816(o[nt], pah, vbl[nt]);
            #pragma unroll
            for (int nt = 0; nt < 8; nt++) mma16816(o[nt], pal, vbh[nt]);
        }
    }

    // ---- normalize + write split fp16 (proj GEMM A operand) ----
    float i0 = 1.0f / l0, i1 = 1.0f / l1;
    int r0 = qb + wid * 16 + (lane >> 2);
    size_t tok0 = (size_t)b * SS + r0;
    size_t base0 = (tok0 * DD + h * HDIM + (lane & 3) * 2) >> 1;
    size_t base1 = base0 + (size_t)4 * DD;   // row + 8
    #pragma unroll
    for (int nt = 0; nt < 8; nt++) {
        uint32_t hv, lv;
        split2h(o[nt][0] * i0, o[nt][1] * i0, hv, lv);
        ohi[base0 + nt * 4] = hv;
        olo[base0 + nt * 4] = lv;
        split2h(o[nt][2] * i1, o[nt][3] * i1, hv, lv);
        ohi[base1 + nt * 4] = hv;
        olo[base1 + nt * 4] = lv;
    }
}

// ---------------------------------------------------------------------------
// Orchestration (graph-capturable: kernel launches only)
// ---------------------------------------------------------------------------
extern "C" void kernel_launch(void* const* d_in, const int* in_sizes, int n_in,
                              void* d_out, int out_size) {
    const int*   idx    = (const int*)  d_in[0];
    const float* wte    = (const float*)d_in[1];
    const float* wpe    = (const float*)d_in[2];
    const float* ln1w   = (const float*)d_in[3];
    const float* ln1b   = (const float*)d_in[4];
    const float* qkvw   = (const float*)d_in[5];
    const float* qkvb   = (const float*)d_in[6];
    const float* projw  = (const float*)d_in[7];
    const float* projb  = (const float*)d_in[8];
    const float* ln2w   = (const float*)d_in[9];
    const float* ln2b   = (const float*)d_in[10];
    const float* fcw    = (const float*)d_in[11];
    const float* fcb    = (const float*)d_in[12];
    const float* cprojw = (const float*)d_in[13];
    const float* cprojb = (const float*)d_in[14];
    const float* lnfw   = (const float*)d_in[15];
    const float* lnfb   = (const float*)d_in[16];
    const float* headw  = (const float*)d_in[17];
    float* out = (float*)d_out;

    float *px, *pq;
    uint32_t *pah, *pal, *pfh, *pfl, *pbh;
    cudaGetSymbolAddress((void**)&px,  g_x);
    cudaGetSymbolAddress((void**)&pq,  g_qkv);
    cudaGetSymbolAddress((void**)&pah, g_ah);
    cudaGetSymbolAddress((void**)&pal, g_al);
    cudaGetSymbolAddress((void**)&pfh, g_fh);
    cudaGetSymbolAddress((void**)&pfl, g_fl);
    cudaGetSymbolAddress((void**)&pbh, g_bh);

    cudaFuncSetAttribute(gemm_bf<0>, cudaFuncAttributeMaxDynamicSharedMemorySize, GEMM_SMEM);
    cudaFuncSetAttribute(gemm_bf<1>, cudaFuncAttributeMaxDynamicSharedMemorySize, GEMM_SMEM);
    cudaFuncSetAttribute(gemm_bf<2>, cudaFuncAttributeMaxDynamicSharedMemorySize, GEMM_SMEM);
    cudaFuncSetAttribute(gemm_bf<3>, cudaFuncAttributeMaxDynamicSharedMemorySize, GEMM_SMEM);

    embed_k<<<MTOK, 256>>>(idx, wte, wpe, px);

    for (int l = 0; l < LL; l++) {
        // --- qkv ---
        ln_k<<<MTOK, 256>>>(px, ln1w + (size_t)l * DD, ln1b + (size_t)l * DD, pah, pal);
        cvt_w<<<3 * DD * DD / 1024, 256>>>(qkvw + (size_t)l * 3 * DD * DD, pbh, 3 * DD * DD / 4);
        gemm_bf<0><<<dim3(3 * DD / 128, MTOK / 128), 256, GEMM_SMEM>>>(
            (const char*)pah, (const char*)pal, (const char*)pbh,
            qkvb + (size_t)l * 3 * DD, pq, nullptr, nullptr, MTOK, 3 * DD, DD);
        // --- attention (tensor-core flash) ---
        attn_k<<<dim3(SS / 64, HH, BB), 128>>>(pq, pah, pal);
        // --- proj (+residual) ---
        cvt_w<<<DD * DD / 1024, 256>>>(projw + (size_t)l * DD * DD, pbh, DD * DD / 4);
        gemm_bf<2><<<dim3(DD / 128, MTOK / 128), 256, GEMM_SMEM>>>(
            (const char*)pah, (const char*)pal, (const char*)pbh,
            projb + (size_t)l * DD, px, nullptr, nullptr, MTOK, DD, DD);
        // --- fc + gelu ---
        ln_k<<<MTOK, 256>>>(px, ln2w + (size_t)l * DD, ln2b + (size_t)l * DD, pah, pal);
        cvt_w<<<4 * DD * DD / 1024, 256>>>(fcw + (size_t)l * 4 * DD * DD, pbh, 4 * DD * DD / 4);
        gemm_bf<1><<<dim3(4 * DD / 128, MTOK / 128), 256, GEMM_SMEM>>>(
            (const char*)pah, (const char*)pal, (const char*)pbh,
            fcb + (size_t)l * 4 * DD, nullptr, pfh, pfl, MTOK, 4 * DD, DD);
        // --- cproj (+residual) ---
        cvt_w<<<DD * 4 * DD / 1024, 256>>>(cprojw + (size_t)l * DD * 4 * DD, pbh, DD * 4 * DD / 4);
        gemm_bf<2><<<dim3(DD / 128, MTOK / 128), 256, GEMM_SMEM>>>(
            (const char*)pfh, (const char*)pfl, (const char*)pbh,
            cprojb + (size_t)l * DD, px, nullptr, nullptr, MTOK, DD, 4 * DD);
    }

    ln_k<<<MTOK, 256>>>(px, lnfw, lnfb, pah, pal);
    cvt_w<<<VV * DD / 1024, 256>>>(headw, pbh, VV * DD / 4);
    gemm_bf<3><<<dim3(VV / 128, MTOK / 128), 256, GEMM_SMEM>>>(
        (const char*)pah, (const char*)pal, (const char*)pbh,
        nullptr, out, nullptr, nullptr, MTOK, VV, DD);
}